// round 5
// baseline (speedup 1.0000x reference)
#include <cuda_runtime.h>
#include <cuda_bf16.h>
#include <cstdint>
#include <math.h>

// Problem dims
#define B_ 512
#define S_ 128
#define D_ 256
#define H_ 4
#define DH_ 64
#define FF_ 384
#define L_ 6
#define ROWS_ (B_ * S_)
#define SCALE_ 0.125f

#define DD_   (D_ * D_)        // 65536
#define D3D_  (3 * D_ * D_)    // 196608
#define FFD_  (FF_ * D_)       // 98304
#define DFF_  (D_ * FF_)       // 98304
#define OFF_PIW 0
#define OFF_POW (L_ * D3D_)                 // 1179648
#define OFF_L1W (OFF_POW + L_ * DD_)        // 1572864
#define OFF_L2W (OFF_L1W + L_ * FFD_)       // 2162688
#define W_TOTAL (OFF_L2W + L_ * DFF_)       // 2752512

// ---------------- scratch (device globals) ----------------------------------
__device__ float g_h  [(size_t)ROWS_ * D_];
__device__ float g_hn [(size_t)ROWS_ * D_];
__device__ float g_qkv[(size_t)ROWS_ * 3 * D_];
__device__ __nv_bfloat16 g_hnH [(size_t)ROWS_ * D_];
__device__ __nv_bfloat16 g_hnL [(size_t)ROWS_ * D_];
__device__ __nv_bfloat16 g_tmpH[(size_t)ROWS_ * FF_];
__device__ __nv_bfloat16 g_tmpL[(size_t)ROWS_ * FF_];
__device__ __nv_bfloat16 g_wH  [W_TOTAL];
__device__ __nv_bfloat16 g_wL  [W_TOTAL];

extern __shared__ char dyn_smem[];

// ======================= helpers ===========================================
__device__ __forceinline__ uint32_t smem_u32(const void* p) {
    uint32_t a;
    asm("{ .reg .u64 t; cvta.to.shared.u64 t, %1; cvt.u32.u64 %0, t; }"
        : "=r"(a) : "l"(p));
    return a;
}
__device__ __forceinline__ void ldsm4(uint32_t a, uint32_t* r) {
    asm volatile("ldmatrix.sync.aligned.m8n8.x4.shared.b16 {%0,%1,%2,%3}, [%4];"
                 : "=r"(r[0]), "=r"(r[1]), "=r"(r[2]), "=r"(r[3]) : "r"(a));
}
__device__ __forceinline__ void ldsm2(uint32_t a, uint32_t* r) {
    asm volatile("ldmatrix.sync.aligned.m8n8.x2.shared.b16 {%0,%1}, [%2];"
                 : "=r"(r[0]), "=r"(r[1]) : "r"(a));
}
__device__ __forceinline__ void mma16816(float* d, const uint32_t* a,
                                         const uint32_t* b) {
    asm volatile("mma.sync.aligned.m16n8k16.row.col.f32.bf16.bf16.f32 "
                 "{%0,%1,%2,%3}, {%4,%5,%6,%7}, {%8,%9}, {%0,%1,%2,%3};"
                 : "+f"(d[0]), "+f"(d[1]), "+f"(d[2]), "+f"(d[3])
                 : "r"(a[0]), "r"(a[1]), "r"(a[2]), "r"(a[3]),
                   "r"(b[0]), "r"(b[1]));
}
// split pair of floats -> packed bf16 hi, packed bf16 lo (2x16 bits each)
__device__ __forceinline__ void split2(float a, float b, uint32_t& hi, uint32_t& lo) {
    __nv_bfloat16 h0 = __float2bfloat16(a);
    __nv_bfloat16 h1 = __float2bfloat16(b);
    __nv_bfloat16 l0 = __float2bfloat16(a - __bfloat162float(h0));
    __nv_bfloat16 l1 = __float2bfloat16(b - __bfloat162float(h1));
    hi = (uint32_t)__bfloat16_as_ushort(h0) | ((uint32_t)__bfloat16_as_ushort(h1) << 16);
    lo = (uint32_t)__bfloat16_as_ushort(l0) | ((uint32_t)__bfloat16_as_ushort(l1) << 16);
}
__device__ __forceinline__ void split8(float4 v0, float4 v1, uint4& hi, uint4& lo) {
    uint32_t h[4], l[4];
    split2(v0.x, v0.y, h[0], l[0]);
    split2(v0.z, v0.w, h[1], l[1]);
    split2(v1.x, v1.y, h[2], l[2]);
    split2(v1.z, v1.w, h[3], l[3]);
    hi = make_uint4(h[0], h[1], h[2], h[3]);
    lo = make_uint4(l[0], l[1], l[2], l[3]);
}

// ---------------- weight preconversion -------------------------------------
__global__ __launch_bounds__(256) void wconv_kernel(
    const float* __restrict__ src, __nv_bfloat16* __restrict__ dh,
    __nv_bfloat16* __restrict__ dl, int n8)
{
    int idx = blockIdx.x * 256 + threadIdx.x;
    if (idx >= n8) return;
    const float* p = src + (size_t)idx * 8;
    float4 v0 = *(const float4*)(p);
    float4 v1 = *(const float4*)(p + 4);
    uint4 hi, lo; split8(v0, v1, hi, lo);
    *(uint4*)(dh + (size_t)idx * 8) = hi;
    *(uint4*)(dl + (size_t)idx * 8) = lo;
}

// ======================= mma.sync GEMM ======================================
// C = A @ W^T, operands pre-split bf16 hi/lo, fp32 accum, bf16x3 (3 passes).
// CTA 128x128, 256 threads (8 warps of 64x32), K chunks of 64.
#define GO_BIAS 0u
#define GO_AH   1024u
#define GO_AL   (1024u + 16384u)
#define GO_WH   (1024u + 32768u)
#define GO_WL   (1024u + 49152u)
#define G_SMEM  (1024 + 4 * 16384)   // 66560

template<bool GELU, bool RES, bool HASB, bool OUTBF>
__global__ __launch_bounds__(256)
void mgemm_kernel(const __nv_bfloat16* __restrict__ Ah,
                  const __nv_bfloat16* __restrict__ Al,
                  const __nv_bfloat16* __restrict__ Wh,
                  const __nv_bfloat16* __restrict__ Wl,
                  const float* __restrict__ bias, const float* __restrict__ res,
                  float* __restrict__ Cf,
                  __nv_bfloat16* __restrict__ Ch, __nv_bfloat16* __restrict__ Cl,
                  int M, int N, int K)
{
    char* smem = dyn_smem;
    const uint32_t sb = smem_u32(smem);
    const int tid  = threadIdx.x;
    const int lane = tid & 31;
    const int warp = tid >> 5;
    const int bm = blockIdx.y << 7;
    const int bn = blockIdx.x << 7;
    const int wm = (warp >> 2) << 6;
    const int wn = (warp & 3) << 5;

    float* sbias = (float*)(smem + GO_BIAS);
    if (HASB && tid < 128) sbias[tid] = bias[bn + tid];

    float acc[4][4][4];
#pragma unroll
    for (int i = 0; i < 4; i++)
#pragma unroll
        for (int j = 0; j < 4; j++)
#pragma unroll
            for (int k = 0; k < 4; k++) acc[i][j][k] = 0.0f;

    const int a_row = lane & 15;
    const int a_cg  = lane >> 4;
    const int b_row = lane & 7;
    const int b_cg  = (lane >> 3) & 1;

    for (int kc = 0; kc < K; kc += 64) {
        __syncthreads();
#pragma unroll
        for (int it = 0; it < 4; it++) {
            int cidx = tid + it * 256;          // 0..1023
            int row = cidx >> 3;
            int g   = cidx & 7;
            uint32_t off = (uint32_t)(row * 128 + ((g ^ (row & 7)) << 4));
            size_t ao = (size_t)(bm + row) * K + kc + g * 8;
            size_t wo = (size_t)(bn + row) * K + kc + g * 8;
            *(uint4*)(smem + GO_AH + off) = *(const uint4*)(Ah + ao);
            *(uint4*)(smem + GO_AL + off) = *(const uint4*)(Al + ao);
            *(uint4*)(smem + GO_WH + off) = *(const uint4*)(Wh + wo);
            *(uint4*)(smem + GO_WL + off) = *(const uint4*)(Wl + wo);
        }
        __syncthreads();

#pragma unroll
        for (int ks = 0; ks < 4; ks++) {
            uint32_t ah[4][4], wh[4][2];
#pragma unroll
            for (int mt = 0; mt < 4; mt++) {
                int row = wm + mt * 16 + a_row;
                int cg  = ks * 2 + a_cg;
                ldsm4(sb + GO_AH + row * 128 + ((cg ^ (row & 7)) << 4), ah[mt]);
            }
#pragma unroll
            for (int nt = 0; nt < 4; nt++) {
                int row = wn + nt * 8 + b_row;
                int cg  = ks * 2 + b_cg;
                ldsm2(sb + GO_WH + row * 128 + ((cg ^ (row & 7)) << 4), wh[nt]);
            }
#pragma unroll
            for (int mt = 0; mt < 4; mt++)
#pragma unroll
                for (int nt = 0; nt < 4; nt++)
                    mma16816(acc[mt][nt], ah[mt], wh[nt]);
#pragma unroll
            for (int mt = 0; mt < 4; mt++) {
                uint32_t al[4];
                int row = wm + mt * 16 + a_row;
                int cg  = ks * 2 + a_cg;
                ldsm4(sb + GO_AL + row * 128 + ((cg ^ (row & 7)) << 4), al);
#pragma unroll
                for (int nt = 0; nt < 4; nt++)
                    mma16816(acc[mt][nt], al, wh[nt]);
            }
#pragma unroll
            for (int nt = 0; nt < 4; nt++) {
                uint32_t wl[2];
                int row = wn + nt * 8 + b_row;
                int cg  = ks * 2 + b_cg;
                ldsm2(sb + GO_WL + row * 128 + ((cg ^ (row & 7)) << 4), wl);
#pragma unroll
                for (int mt = 0; mt < 4; mt++)
                    mma16816(acc[mt][nt], ah[mt], wl);
            }
        }
    }

    // ---- epilogue ----
#pragma unroll
    for (int mt = 0; mt < 4; mt++) {
        int r = bm + wm + mt * 16 + (lane >> 2);
#pragma unroll
        for (int nt = 0; nt < 4; nt++) {
            int cl = wn + nt * 8 + ((lane & 3) << 1);
            int c  = bn + cl;
            float2 v0 = make_float2(acc[mt][nt][0], acc[mt][nt][1]);
            float2 v1 = make_float2(acc[mt][nt][2], acc[mt][nt][3]);
            if (HASB) {
                float b0 = sbias[cl], b1 = sbias[cl + 1];
                v0.x += b0; v0.y += b1; v1.x += b0; v1.y += b1;
            }
            if (GELU) {
                v0.x = 0.5f * v0.x * (1.0f + erff(v0.x * 0.70710678f));
                v0.y = 0.5f * v0.y * (1.0f + erff(v0.y * 0.70710678f));
                v1.x = 0.5f * v1.x * (1.0f + erff(v1.x * 0.70710678f));
                v1.y = 0.5f * v1.y * (1.0f + erff(v1.y * 0.70710678f));
            }
            size_t i0 = (size_t)r * N + c;
            size_t i1 = (size_t)(r + 8) * N + c;
            if (OUTBF) {
                uint32_t hi, lo;
                split2(v0.x, v0.y, hi, lo);
                *(uint32_t*)(Ch + i0) = hi;
                *(uint32_t*)(Cl + i0) = lo;
                split2(v1.x, v1.y, hi, lo);
                *(uint32_t*)(Ch + i1) = hi;
                *(uint32_t*)(Cl + i1) = lo;
            } else {
                if (RES) {
                    float2 r0 = *(const float2*)(res + i0);
                    float2 r1 = *(const float2*)(res + i1);
                    v0.x += r0.x; v0.y += r0.y; v1.x += r1.x; v1.y += r1.y;
                }
                *(float2*)(Cf + i0) = v0;
                *(float2*)(Cf + i1) = v1;
            }
        }
    }
}

// ---------------- embedding + positional encoding ---------------------------
__global__ __launch_bounds__(256) void embed_kernel(
    const int* __restrict__ x, const float* __restrict__ ew,
    float* __restrict__ h)
{
    int row = blockIdx.x;
    int d   = threadIdx.x;
    int s   = row & (S_ - 1);
    int tok = x[row];
    int p   = d >> 1;
    float dim_t = powf(10000.0f, (float)p * (1.0f / 128.0f));
    float pos   = (float)s / dim_t;
    float pe    = (d & 1) ? cosf(pos) : sinf(pos);
    h[(size_t)row * D_ + d] = ew[(size_t)tok * D_ + d] + pe;
}

// ---------------- LayerNorm + bf16 hi/lo emit --------------------------------
__global__ __launch_bounds__(256) void ln_kernel(
    const float* __restrict__ in, float* __restrict__ out,
    __nv_bfloat16* __restrict__ outH, __nv_bfloat16* __restrict__ outL,
    const float* __restrict__ w, const float* __restrict__ b)
{
    int warp = threadIdx.x >> 5, lane = threadIdx.x & 31;
    size_t row = (size_t)blockIdx.x * 8 + warp;
    const float* p = in + row * D_;
    float4 a0 = *(const float4*)(p + lane * 4);
    float4 a1 = *(const float4*)(p + 128 + lane * 4);
    float s = a0.x + a0.y + a0.z + a0.w + a1.x + a1.y + a1.z + a1.w;
    float q = a0.x*a0.x + a0.y*a0.y + a0.z*a0.z + a0.w*a0.w
            + a1.x*a1.x + a1.y*a1.y + a1.z*a1.z + a1.w*a1.w;
#pragma unroll
    for (int o = 16; o > 0; o >>= 1) {
        s += __shfl_xor_sync(0xffffffffu, s, o);
        q += __shfl_xor_sync(0xffffffffu, q, o);
    }
    float mean = s * (1.0f / 256.0f);
    float var  = q * (1.0f / 256.0f) - mean * mean;
    float rstd = rsqrtf(var + 1e-5f);
    float4 w0 = *(const float4*)(w + lane * 4);
    float4 w1 = *(const float4*)(w + 128 + lane * 4);
    float4 b0 = *(const float4*)(b + lane * 4);
    float4 b1 = *(const float4*)(b + 128 + lane * 4);
    float4 o0, o1;
    o0.x = (a0.x - mean) * rstd * w0.x + b0.x;
    o0.y = (a0.y - mean) * rstd * w0.y + b0.y;
    o0.z = (a0.z - mean) * rstd * w0.z + b0.z;
    o0.w = (a0.w - mean) * rstd * w0.w + b0.w;
    o1.x = (a1.x - mean) * rstd * w1.x + b1.x;
    o1.y = (a1.y - mean) * rstd * w1.y + b1.y;
    o1.z = (a1.z - mean) * rstd * w1.z + b1.z;
    o1.w = (a1.w - mean) * rstd * w1.w + b1.w;
    float* po = out + row * D_;
    *(float4*)(po + lane * 4)       = o0;
    *(float4*)(po + 128 + lane * 4) = o1;
    uint32_t h0, l0, h1, l1;
    split2(o0.x, o0.y, h0, l0); split2(o0.z, o0.w, h1, l1);
    *(uint2*)(outH + row * D_ + lane * 4) = make_uint2(h0, h1);
    *(uint2*)(outL + row * D_ + lane * 4) = make_uint2(l0, l1);
    split2(o1.x, o1.y, h0, l0); split2(o1.z, o1.w, h1, l1);
    *(uint2*)(outH + row * D_ + 128 + lane * 4) = make_uint2(h0, h1);
    *(uint2*)(outL + row * D_ + 128 + lane * 4) = make_uint2(l0, l1);
}

// ---------------- attention: flash-style, thread-pair per query row ----------
// 256 threads: thread t handles query row t>>1, dim-half t&1 (interleaved
// 16B groups gi = 2*i + hf, conflict-free pair LDS). One shfl completes dots.
#define ATTN_SMEM ((2 * 128 * 64 + 128) * 4)   // 66048

__global__ __launch_bounds__(256) void attn_kernel(
    const float* __restrict__ qkv, const float* __restrict__ ids,
    __nv_bfloat16* __restrict__ oh, __nv_bfloat16* __restrict__ ol)
{
    float* sm = (float*)dyn_smem;
    float* Ks  = sm;
    float* Vs  = sm + 128 * 64;
    float* msk = sm + 2 * 128 * 64;
    int h = blockIdx.x, b = blockIdx.y, t = threadIdx.x;
    const float* base = qkv + (size_t)b * S_ * (3 * D_);
    const int qoff = h * DH_;
    const int koff = D_ + h * DH_;
    const int voff = 2 * D_ + h * DH_;

    for (int idx = t; idx < 128 * 16; idx += 256) {
        int r = idx >> 4, c = (idx & 15) << 2;
        *(float4*)(Ks + r * 64 + c) = *(const float4*)(base + (size_t)r * 768 + koff + c);
        *(float4*)(Vs + r * 64 + c) = *(const float4*)(base + (size_t)r * 768 + voff + c);
    }
    if (t < 128) msk[t] = ids[b * S_ + t] * -1e9f;

    const int qr = t >> 1;
    const int hf = t & 1;
    float q[32];
    {
        const float* qp = base + (size_t)qr * 768 + qoff;
#pragma unroll
        for (int i = 0; i < 8; i++) {
            float4 v = *(const float4*)(qp + (2 * i + hf) * 4);
            q[i*4] = v.x; q[i*4+1] = v.y; q[i*4+2] = v.z; q[i*4+3] = v.w;
        }
    }
    __syncthreads();

    float m = -1e30f, l = 0.0f;
    float o[32];
#pragma unroll
    for (int i = 0; i < 32; i++) o[i] = 0.0f;

    for (int j0 = 0; j0 < 128; j0 += 16) {
        float s[16];
        float cm = -1e30f;
#pragma unroll
        for (int jj = 0; jj < 16; jj++) {
            const float* kr = Ks + (j0 + jj) * 64;
            float dot = 0.0f;
#pragma unroll
            for (int i = 0; i < 8; i++) {
                float4 kv = *(const float4*)(kr + (2 * i + hf) * 4);
                dot = fmaf(q[i*4],   kv.x, dot);
                dot = fmaf(q[i*4+1], kv.y, dot);
                dot = fmaf(q[i*4+2], kv.z, dot);
                dot = fmaf(q[i*4+3], kv.w, dot);
            }
            dot += __shfl_xor_sync(0xffffffffu, dot, 1);
            float sc = (dot + msk[j0 + jj]) * SCALE_;
            s[jj] = sc;
            cm = fmaxf(cm, sc);
        }
        float mn = fmaxf(m, cm);
        float corr = __expf(m - mn);
        l *= corr;
#pragma unroll
        for (int i = 0; i < 32; i++) o[i] *= corr;
#pragma unroll
        for (int jj = 0; jj < 16; jj++) {
            float pr = __expf(s[jj] - mn);
            l += pr;
            const float* vr = Vs + (j0 + jj) * 64;
#pragma unroll
            for (int i = 0; i < 8; i++) {
                float4 vv = *(const float4*)(vr + (2 * i + hf) * 4);
                o[i*4]   = fmaf(pr, vv.x, o[i*4]);
                o[i*4+1] = fmaf(pr, vv.y, o[i*4+1]);
                o[i*4+2] = fmaf(pr, vv.z, o[i*4+2]);
                o[i*4+3] = fmaf(pr, vv.w, o[i*4+3]);
            }
        }
        m = mn;
    }
    float inv = 1.0f / l;
    size_t obase = (size_t)(b * S_ + qr) * D_ + h * DH_;
#pragma unroll
    for (int i = 0; i < 8; i++) {
        int gi = 2 * i + hf;
        float v0 = o[i*4] * inv,   v1 = o[i*4+1] * inv;
        float v2 = o[i*4+2] * inv, v3 = o[i*4+3] * inv;
        uint32_t h0, l0, h1, l1;
        split2(v0, v1, h0, l0);
        split2(v2, v3, h1, l1);
        *(uint2*)(oh + obase + gi * 4) = make_uint2(h0, h1);
        *(uint2*)(ol + obase + gi * 4) = make_uint2(l0, l1);
    }
}

// ---------------- final logits ---------------------------------------------
__global__ __launch_bounds__(256) void logits_kernel(
    const float* __restrict__ hflat, const float* __restrict__ W,
    const float* __restrict__ bias, float* __restrict__ out)
{
    int b = blockIdx.x, t = threadIdx.x;
    const float4* h4  = (const float4*)(hflat + (size_t)b * 32768);
    const float4* w04 = (const float4*)(W);
    const float4* w14 = (const float4*)(W + 32768);
    float a0 = 0.0f, a1 = 0.0f;
    for (int i = t; i < 8192; i += 256) {
        float4 x = h4[i], u = w04[i], v = w14[i];
        a0 += x.x*u.x + x.y*u.y + x.z*u.z + x.w*u.w;
        a1 += x.x*v.x + x.y*v.y + x.z*v.z + x.w*v.w;
    }
    __shared__ float r0[256], r1[256];
    r0[t] = a0; r1[t] = a1;
    __syncthreads();
    for (int s = 128; s > 0; s >>= 1) {
        if (t < s) { r0[t] += r0[t + s]; r1[t] += r1[t + s]; }
        __syncthreads();
    }
    if (t == 0) {
        out[b * 2 + 0] = r0[0] + bias[0];
        out[b * 2 + 1] = r1[0] + bias[1];
    }
}

// ---------------- launch ----------------------------------------------------
extern "C" void kernel_launch(void* const* d_in, const int* in_sizes, int n_in,
                              void* d_out, int out_size)
{
    const int*   x    = (const int*)  d_in[0];
    const float* ids  = (const float*)d_in[1];
    const float* ew   = (const float*)d_in[2];
    const float* n1w  = (const float*)d_in[3];
    const float* n1b  = (const float*)d_in[4];
    const float* piw  = (const float*)d_in[5];
    const float* pow_ = (const float*)d_in[6];
    const float* pob  = (const float*)d_in[7];
    const float* n2w  = (const float*)d_in[8];
    const float* n2b  = (const float*)d_in[9];
    const float* l1w  = (const float*)d_in[10];
    const float* l1b  = (const float*)d_in[11];
    const float* l2w  = (const float*)d_in[12];
    const float* l2b  = (const float*)d_in[13];
    const float* lw   = (const float*)d_in[14];
    const float* lb   = (const float*)d_in[15];
    float* out = (float*)d_out;

    float *h, *hn, *qkvb;
    __nv_bfloat16 *hnH, *hnL, *tmpH, *tmpL, *wH, *wL;
    cudaGetSymbolAddress((void**)&h,    g_h);
    cudaGetSymbolAddress((void**)&hn,   g_hn);
    cudaGetSymbolAddress((void**)&qkvb, g_qkv);
    cudaGetSymbolAddress((void**)&hnH,  g_hnH);
    cudaGetSymbolAddress((void**)&hnL,  g_hnL);
    cudaGetSymbolAddress((void**)&tmpH, g_tmpH);
    cudaGetSymbolAddress((void**)&tmpL, g_tmpL);
    cudaGetSymbolAddress((void**)&wH,   g_wH);
    cudaGetSymbolAddress((void**)&wL,   g_wL);

    cudaFuncSetAttribute(attn_kernel,
                         cudaFuncAttributeMaxDynamicSharedMemorySize, ATTN_SMEM);
    cudaFuncSetAttribute(mgemm_kernel<false,false,false,false>,
                         cudaFuncAttributeMaxDynamicSharedMemorySize, G_SMEM);
    cudaFuncSetAttribute(mgemm_kernel<false,true,true,false>,
                         cudaFuncAttributeMaxDynamicSharedMemorySize, G_SMEM);
    cudaFuncSetAttribute(mgemm_kernel<true,false,true,true>,
                         cudaFuncAttributeMaxDynamicSharedMemorySize, G_SMEM);

    // preconvert all weights to bf16 hi/lo (once per launch)
    wconv_kernel<<<(L_ * D3D_ / 8 + 255) / 256, 256>>>(piw,  wH + OFF_PIW, wL + OFF_PIW, L_ * D3D_ / 8);
    wconv_kernel<<<(L_ * DD_  / 8 + 255) / 256, 256>>>(pow_, wH + OFF_POW, wL + OFF_POW, L_ * DD_ / 8);
    wconv_kernel<<<(L_ * FFD_ / 8 + 255) / 256, 256>>>(l1w,  wH + OFF_L1W, wL + OFF_L1W, L_ * FFD_ / 8);
    wconv_kernel<<<(L_ * DFF_ / 8 + 255) / 256, 256>>>(l2w,  wH + OFF_L2W, wL + OFF_L2W, L_ * DFF_ / 8);

    embed_kernel<<<ROWS_, 256>>>(x, ew, h);

    for (int l = 0; l < L_; l++) {
        ln_kernel<<<ROWS_ / 8, 256>>>(h, hn, hnH, hnL, n1w + l * D_, n1b + l * D_);
        mgemm_kernel<false,false,false,false><<<dim3(6, 512), 256, G_SMEM>>>(
            hnH, hnL, wH + OFF_PIW + (size_t)l * D3D_, wL + OFF_PIW + (size_t)l * D3D_,
            nullptr, nullptr, qkvb, nullptr, nullptr, ROWS_, 3 * D_, D_);
        attn_kernel<<<dim3(H_, B_), 256, ATTN_SMEM>>>(qkvb, ids, tmpH, tmpL);
        mgemm_kernel<false,true,true,false><<<dim3(2, 512), 256, G_SMEM>>>(
            tmpH, tmpL, wH + OFF_POW + (size_t)l * DD_, wL + OFF_POW + (size_t)l * DD_,
            pob + l * D_, hn, h, nullptr, nullptr, ROWS_, D_, D_);
        ln_kernel<<<ROWS_ / 8, 256>>>(h, hn, hnH, hnL, n2w + l * D_, n2b + l * D_);
        mgemm_kernel<true,false,true,true><<<dim3(3, 512), 256, G_SMEM>>>(
            hnH, hnL, wH + OFF_L1W + (size_t)l * FFD_, wL + OFF_L1W + (size_t)l * FFD_,
            l1b + l * FF_, nullptr, nullptr, tmpH, tmpL, ROWS_, FF_, D_);
        mgemm_kernel<false,true,true,false><<<dim3(2, 512), 256, G_SMEM>>>(
            tmpH, tmpL, wH + OFF_L2W + (size_t)l * DFF_, wL + OFF_L2W + (size_t)l * DFF_,
            l2b + l * D_, hn, h, nullptr, nullptr, ROWS_, D_, FF_);
    }

    logits_kernel<<<B_, 256>>>(h, lw, lb, out);
}

// round 7
// speedup vs baseline: 1.8519x; 1.8519x over previous
#include <cuda_runtime.h>
#include <cuda_fp16.h>
#include <cstdint>
#include <math.h>

// Problem dims
#define B_ 512
#define S_ 128
#define D_ 256
#define H_ 4
#define DH_ 64
#define FF_ 384
#define L_ 6
#define ROWS_ (B_ * S_)
#define SCALE_ 0.125f

#define DD_   (D_ * D_)
#define D3D_  (3 * D_ * D_)
#define FFD_  (FF_ * D_)
#define DFF_  (D_ * FF_)
#define OFF_PIW 0
#define OFF_POW (L_ * D3D_)
#define OFF_L1W (OFF_POW + L_ * DD_)
#define OFF_L2W (OFF_L1W + L_ * FFD_)
#define W_TOTAL (OFF_L2W + L_ * DFF_)

// ---------------- scratch (device globals) ----------------------------------
__device__ float g_h  [(size_t)ROWS_ * D_];
__device__ float g_hn [(size_t)ROWS_ * D_];
__device__ float g_qkv[(size_t)ROWS_ * 3 * D_];
__device__ __half g_hnH [(size_t)ROWS_ * D_];
__device__ __half g_tmpH[(size_t)ROWS_ * FF_];
__device__ __half g_wH  [W_TOTAL];

extern __shared__ char dyn_smem[];

// ======================= helpers ===========================================
__device__ __forceinline__ uint32_t smem_u32(const void* p) {
    uint32_t a;
    asm("{ .reg .u64 t; cvta.to.shared.u64 t, %1; cvt.u32.u64 %0, t; }"
        : "=r"(a) : "l"(p));
    return a;
}
__device__ __forceinline__ void ldsm4(uint32_t a, uint32_t* r) {
    asm volatile("ldmatrix.sync.aligned.m8n8.x4.shared.b16 {%0,%1,%2,%3}, [%4];"
                 : "=r"(r[0]), "=r"(r[1]), "=r"(r[2]), "=r"(r[3]) : "r"(a));
}
__device__ __forceinline__ void ldsm2(uint32_t a, uint32_t* r) {
    asm volatile("ldmatrix.sync.aligned.m8n8.x2.shared.b16 {%0,%1}, [%2];"
                 : "=r"(r[0]), "=r"(r[1]) : "r"(a));
}
__device__ __forceinline__ void mma16816h(float* d, const uint32_t* a,
                                          const uint32_t* b) {
    asm volatile("mma.sync.aligned.m16n8k16.row.col.f32.f16.f16.f32 "
                 "{%0,%1,%2,%3}, {%4,%5,%6,%7}, {%8,%9}, {%0,%1,%2,%3};"
                 : "+f"(d[0]), "+f"(d[1]), "+f"(d[2]), "+f"(d[3])
                 : "r"(a[0]), "r"(a[1]), "r"(a[2]), "r"(a[3]),
                   "r"(b[0]), "r"(b[1]));
}
__device__ __forceinline__ uint32_t pack2h(float a, float b) {
    __half2 h = __floats2half2_rn(a, b);
    uint32_t r;
    memcpy(&r, &h, 4);
    return r;
}
__device__ __forceinline__ void cp_async16(uint32_t sa, const void* ga) {
    asm volatile("cp.async.cg.shared.global [%0], [%1], 16;"
                 :: "r"(sa), "l"(ga) : "memory");
}
#define CP_COMMIT() asm volatile("cp.async.commit_group;" ::: "memory")
#define CP_WAIT(N)  asm volatile("cp.async.wait_group %0;" :: "n"(N) : "memory")

// ---------------- weight preconversion (fp32 -> fp16) ------------------------
__global__ __launch_bounds__(256) void wconv_kernel(
    const float* __restrict__ src, __half* __restrict__ dst, int n8)
{
    int idx = blockIdx.x * 256 + threadIdx.x;
    if (idx >= n8) return;
    const float* p = src + (size_t)idx * 8;
    float4 v0 = *(const float4*)(p);
    float4 v1 = *(const float4*)(p + 4);
    uint4 o;
    o.x = pack2h(v0.x, v0.y);
    o.y = pack2h(v0.z, v0.w);
    o.z = pack2h(v1.x, v1.y);
    o.w = pack2h(v1.z, v1.w);
    *(uint4*)(dst + (size_t)idx * 8) = o;
}

// ======================= fp16 mma GEMM ======================================
// C[M,N] = A[M,K] @ W[N,K]^T (+bias)(+gelu)(+res), fp16 operands, fp32 accum.
// CTA 128x128, 256 threads (8 warps of 64x32), K chunks of 64,
// cp.async double-buffered staging.
#define GO_BIAS  0u
#define GO_STAGE 1024u
#define STAGE_SZ 32768u          // A tile 16K + W tile 16K
#define G_SMEM   (1024 + 2 * 32768)   // 66560

// issue K-chunk c into stage (c&1): 8 cp.async per thread
__device__ __forceinline__ void gemm_issue_chunk(
    uint32_t sb, const __half* A, const __half* W,
    int bm, int bn, int K, int c, int s_row, int s_g, uint32_t s_off)
{
    const int kc = c << 6;
    const uint32_t stage = GO_STAGE + (uint32_t)(c & 1) * STAGE_SZ;
#pragma unroll
    for (int it = 0; it < 4; it++) {
        uint32_t off = s_off + (uint32_t)(it * 32 * 128);
        int row = s_row + it * 32;
        cp_async16(sb + stage + off,
                   A + (size_t)(bm + row) * K + kc + s_g * 8);
        cp_async16(sb + stage + 16384 + off,
                   W + (size_t)(bn + row) * K + kc + s_g * 8);
    }
    CP_COMMIT();
}

template<bool GELU, bool RES, bool HASB, bool OUTH>
__global__ __launch_bounds__(256)
void mgemm_kernel(const __half* __restrict__ A, const __half* __restrict__ W,
                  const float* __restrict__ bias, const float* __restrict__ res,
                  float* __restrict__ Cf, __half* __restrict__ Ch,
                  int M, int N, int K)
{
    char* smem = dyn_smem;
    const uint32_t sb = smem_u32(smem);
    const int tid  = threadIdx.x;
    const int lane = tid & 31;
    const int warp = tid >> 5;
    const int bm = blockIdx.y << 7;
    const int bn = blockIdx.x << 7;
    const int wm = (warp >> 2) << 6;
    const int wn = (warp & 3) << 5;

    float* sbias = (float*)(smem + GO_BIAS);
    if (HASB && tid < 128) sbias[tid] = bias[bn + tid];

    float acc[4][4][4];
#pragma unroll
    for (int i = 0; i < 4; i++)
#pragma unroll
        for (int j = 0; j < 4; j++)
#pragma unroll
            for (int k = 0; k < 4; k++) acc[i][j][k] = 0.0f;

    const int a_row = lane & 15;
    const int a_cg  = lane >> 4;
    const int b_row = lane & 7;
    const int b_cg  = (lane >> 3) & 1;

    const int s_row = tid >> 3;
    const int s_g   = tid & 7;
    const uint32_t s_off =
        (uint32_t)(s_row * 128 + ((s_g ^ (s_row & 7)) << 4));

    const int nch = K >> 6;

    gemm_issue_chunk(sb, A, W, bm, bn, K, 0, s_row, s_g, s_off);
    for (int c = 0; c < nch; c++) {
        if (c + 1 < nch) {
            gemm_issue_chunk(sb, A, W, bm, bn, K, c + 1, s_row, s_g, s_off);
            CP_WAIT(1);
        } else {
            CP_WAIT(0);
        }
        __syncthreads();

        const uint32_t sA = sb + GO_STAGE + (uint32_t)(c & 1) * STAGE_SZ;
        const uint32_t sW = sA + 16384;
#pragma unroll
        for (int ks = 0; ks < 4; ks++) {
            uint32_t ah[4][4], wh[4][2];
#pragma unroll
            for (int mt = 0; mt < 4; mt++) {
                int row = wm + mt * 16 + a_row;
                int cg  = ks * 2 + a_cg;
                ldsm4(sA + row * 128 + ((cg ^ (row & 7)) << 4), ah[mt]);
            }
#pragma unroll
            for (int nt = 0; nt < 4; nt++) {
                int row = wn + nt * 8 + b_row;
                int cg  = ks * 2 + b_cg;
                ldsm2(sW + row * 128 + ((cg ^ (row & 7)) << 4), wh[nt]);
            }
#pragma unroll
            for (int mt = 0; mt < 4; mt++)
#pragma unroll
                for (int nt = 0; nt < 4; nt++)
                    mma16816h(acc[mt][nt], ah[mt], wh[nt]);
        }
        __syncthreads();
    }

    // ---- epilogue ----
#pragma unroll
    for (int mt = 0; mt < 4; mt++) {
        int r = bm + wm + mt * 16 + (lane >> 2);
#pragma unroll
        for (int nt = 0; nt < 4; nt++) {
            int cl = wn + nt * 8 + ((lane & 3) << 1);
            int c  = bn + cl;
            float2 v0 = make_float2(acc[mt][nt][0], acc[mt][nt][1]);
            float2 v1 = make_float2(acc[mt][nt][2], acc[mt][nt][3]);
            if (HASB) {
                float b0 = sbias[cl], b1 = sbias[cl + 1];
                v0.x += b0; v0.y += b1; v1.x += b0; v1.y += b1;
            }
            if (GELU) {
                v0.x = 0.5f * v0.x * (1.0f + erff(v0.x * 0.70710678f));
                v0.y = 0.5f * v0.y * (1.0f + erff(v0.y * 0.70710678f));
                v1.x = 0.5f * v1.x * (1.0f + erff(v1.x * 0.70710678f));
                v1.y = 0.5f * v1.y * (1.0f + erff(v1.y * 0.70710678f));
            }
            size_t i0 = (size_t)r * N + c;
            size_t i1 = (size_t)(r + 8) * N + c;
            if (OUTH) {
                *(uint32_t*)(Ch + i0) = pack2h(v0.x, v0.y);
                *(uint32_t*)(Ch + i1) = pack2h(v1.x, v1.y);
            } else {
                if (RES) {
                    float2 r0 = *(const float2*)(res + i0);
                    float2 r1 = *(const float2*)(res + i1);
                    v0.x += r0.x; v0.y += r0.y; v1.x += r1.x; v1.y += r1.y;
                }
                *(float2*)(Cf + i0) = v0;
                *(float2*)(Cf + i1) = v1;
            }
        }
    }
}

// ---------------- embedding + positional encoding ---------------------------
__global__ __launch_bounds__(256) void embed_kernel(
    const int* __restrict__ x, const float* __restrict__ ew,
    float* __restrict__ h)
{
    int row = blockIdx.x;
    int d   = threadIdx.x;
    int s   = row & (S_ - 1);
    int tok = x[row];
    int p   = d >> 1;
    float dim_t = powf(10000.0f, (float)p * (1.0f / 128.0f));
    float pos   = (float)s / dim_t;
    float pe    = (d & 1) ? cosf(pos) : sinf(pos);
    h[(size_t)row * D_ + d] = ew[(size_t)tok * D_ + d] + pe;
}

// ---------------- LayerNorm + fp16 emit --------------------------------------
__global__ __launch_bounds__(256) void ln_kernel(
    const float* __restrict__ in, float* __restrict__ out,
    __half* __restrict__ outH,
    const float* __restrict__ w, const float* __restrict__ b)
{
    int warp = threadIdx.x >> 5, lane = threadIdx.x & 31;
    size_t row = (size_t)blockIdx.x * 8 + warp;
    const float* p = in + row * D_;
    float4 a0 = *(const float4*)(p + lane * 4);
    float4 a1 = *(const float4*)(p + 128 + lane * 4);
    float s = a0.x + a0.y + a0.z + a0.w + a1.x + a1.y + a1.z + a1.w;
    float q = a0.x*a0.x + a0.y*a0.y + a0.z*a0.z + a0.w*a0.w
            + a1.x*a1.x + a1.y*a1.y + a1.z*a1.z + a1.w*a1.w;
#pragma unroll
    for (int o = 16; o > 0; o >>= 1) {
        s += __shfl_xor_sync(0xffffffffu, s, o);
        q += __shfl_xor_sync(0xffffffffu, q, o);
    }
    float mean = s * (1.0f / 256.0f);
    float var  = q * (1.0f / 256.0f) - mean * mean;
    float rstd = rsqrtf(var + 1e-5f);
    float4 w0 = *(const float4*)(w + lane * 4);
    float4 w1 = *(const float4*)(w + 128 + lane * 4);
    float4 b0 = *(const float4*)(b + lane * 4);
    float4 b1 = *(const float4*)(b + 128 + lane * 4);
    float4 o0, o1;
    o0.x = (a0.x - mean) * rstd * w0.x + b0.x;
    o0.y = (a0.y - mean) * rstd * w0.y + b0.y;
    o0.z = (a0.z - mean) * rstd * w0.z + b0.z;
    o0.w = (a0.w - mean) * rstd * w0.w + b0.w;
    o1.x = (a1.x - mean) * rstd * w1.x + b1.x;
    o1.y = (a1.y - mean) * rstd * w1.y + b1.y;
    o1.z = (a1.z - mean) * rstd * w1.z + b1.z;
    o1.w = (a1.w - mean) * rstd * w1.w + b1.w;
    float* po = out + row * D_;
    *(float4*)(po + lane * 4)       = o0;
    *(float4*)(po + 128 + lane * 4) = o1;
    *(uint2*)(outH + row * D_ + lane * 4) =
        make_uint2(pack2h(o0.x, o0.y), pack2h(o0.z, o0.w));
    *(uint2*)(outH + row * D_ + 128 + lane * 4) =
        make_uint2(pack2h(o1.x, o1.y), pack2h(o1.z, o1.w));
}

// ---------------- attention: flash-style, thread-pair per query row ----------
#define ATTN_SMEM ((2 * 128 * 64 + 128) * 4)   // 66048

__global__ __launch_bounds__(256) void attn_kernel(
    const float* __restrict__ qkv, const float* __restrict__ ids,
    __half* __restrict__ oh)
{
    float* sm = (float*)dyn_smem;
    float* Ks  = sm;
    float* Vs  = sm + 128 * 64;
    float* msk = sm + 2 * 128 * 64;
    int h = blockIdx.x, b = blockIdx.y, t = threadIdx.x;
    const float* base = qkv + (size_t)b * S_ * (3 * D_);
    const int qoff = h * DH_;
    const int koff = D_ + h * DH_;
    const int voff = 2 * D_ + h * DH_;

    for (int idx = t; idx < 128 * 16; idx += 256) {
        int r = idx >> 4, c = (idx & 15) << 2;
        *(float4*)(Ks + r * 64 + c) = *(const float4*)(base + (size_t)r * 768 + koff + c);
        *(float4*)(Vs + r * 64 + c) = *(const float4*)(base + (size_t)r * 768 + voff + c);
    }
    if (t < 128) msk[t] = ids[b * S_ + t] * -1e9f;

    const int qr = t >> 1;
    const int hf = t & 1;
    float q[32];
    {
        const float* qp = base + (size_t)qr * 768 + qoff;
#pragma unroll
        for (int i = 0; i < 8; i++) {
            float4 v = *(const float4*)(qp + (2 * i + hf) * 4);
            q[i*4] = v.x; q[i*4+1] = v.y; q[i*4+2] = v.z; q[i*4+3] = v.w;
        }
    }
    __syncthreads();

    float m = -1e30f, l = 0.0f;
    float o[32];
#pragma unroll
    for (int i = 0; i < 32; i++) o[i] = 0.0f;

    for (int j0 = 0; j0 < 128; j0 += 16) {
        float s[16];
        float cm = -1e30f;
#pragma unroll
        for (int jj = 0; jj < 16; jj++) {
            const float* kr = Ks + (j0 + jj) * 64;
            float dot = 0.0f;
#pragma unroll
            for (int i = 0; i < 8; i++) {
                float4 kv = *(const float4*)(kr + (2 * i + hf) * 4);
                dot = fmaf(q[i*4],   kv.x, dot);
                dot = fmaf(q[i*4+1], kv.y, dot);
                dot = fmaf(q[i*4+2], kv.z, dot);
                dot = fmaf(q[i*4+3], kv.w, dot);
            }
            dot += __shfl_xor_sync(0xffffffffu, dot, 1);
            float sc = (dot + msk[j0 + jj]) * SCALE_;
            s[jj] = sc;
            cm = fmaxf(cm, sc);
        }
        float mn = fmaxf(m, cm);
        float corr = __expf(m - mn);
        l *= corr;
#pragma unroll
        for (int i = 0; i < 32; i++) o[i] *= corr;
#pragma unroll
        for (int jj = 0; jj < 16; jj++) {
            float pr = __expf(s[jj] - mn);
            l += pr;
            const float* vr = Vs + (j0 + jj) * 64;
#pragma unroll
            for (int i = 0; i < 8; i++) {
                float4 vv = *(const float4*)(vr + (2 * i + hf) * 4);
                o[i*4]   = fmaf(pr, vv.x, o[i*4]);
                o[i*4+1] = fmaf(pr, vv.y, o[i*4+1]);
                o[i*4+2] = fmaf(pr, vv.z, o[i*4+2]);
                o[i*4+3] = fmaf(pr, vv.w, o[i*4+3]);
            }
        }
        m = mn;
    }
    float inv = 1.0f / l;
    size_t obase = (size_t)(b * S_ + qr) * D_ + h * DH_;
#pragma unroll
    for (int i = 0; i < 8; i++) {
        int gi = 2 * i + hf;
        *(uint2*)(oh + obase + gi * 4) =
            make_uint2(pack2h(o[i*4] * inv,   o[i*4+1] * inv),
                       pack2h(o[i*4+2] * inv, o[i*4+3] * inv));
    }
}

// ---------------- final logits ---------------------------------------------
__global__ __launch_bounds__(256) void logits_kernel(
    const float* __restrict__ hflat, const float* __restrict__ W,
    const float* __restrict__ bias, float* __restrict__ out)
{
    int b = blockIdx.x, t = threadIdx.x;
    const float4* h4  = (const float4*)(hflat + (size_t)b * 32768);
    const float4* w04 = (const float4*)(W);
    const float4* w14 = (const float4*)(W + 32768);
    float a0 = 0.0f, a1 = 0.0f;
    for (int i = t; i < 8192; i += 256) {
        float4 x = h4[i], u = w04[i], v = w14[i];
        a0 += x.x*u.x + x.y*u.y + x.z*u.z + x.w*u.w;
        a1 += x.x*v.x + x.y*v.y + x.z*v.z + x.w*v.w;
    }
    __shared__ float r0[256], r1[256];
    r0[t] = a0; r1[t] = a1;
    __syncthreads();
    for (int s = 128; s > 0; s >>= 1) {
        if (t < s) { r0[t] += r0[t + s]; r1[t] += r1[t + s]; }
        __syncthreads();
    }
    if (t == 0) {
        out[b * 2 + 0] = r0[0] + bias[0];
        out[b * 2 + 1] = r1[0] + bias[1];
    }
}

// ---------------- launch ----------------------------------------------------
extern "C" void kernel_launch(void* const* d_in, const int* in_sizes, int n_in,
                              void* d_out, int out_size)
{
    const int*   x    = (const int*)  d_in[0];
    const float* ids  = (const float*)d_in[1];
    const float* ew   = (const float*)d_in[2];
    const float* n1w  = (const float*)d_in[3];
    const float* n1b  = (const float*)d_in[4];
    const float* piw  = (const float*)d_in[5];
    const float* pow_ = (const float*)d_in[6];
    const float* pob  = (const float*)d_in[7];
    const float* n2w  = (const float*)d_in[8];
    const float* n2b  = (const float*)d_in[9];
    const float* l1w  = (const float*)d_in[10];
    const float* l1b  = (const float*)d_in[11];
    const float* l2w  = (const float*)d_in[12];
    const float* l2b  = (const float*)d_in[13];
    const float* lw   = (const float*)d_in[14];
    const float* lb   = (const float*)d_in[15];
    float* out = (float*)d_out;

    float *h, *hn, *qkvb;
    __half *hnH, *tmpH, *wH;
    cudaGetSymbolAddress((void**)&h,    g_h);
    cudaGetSymbolAddress((void**)&hn,   g_hn);
    cudaGetSymbolAddress((void**)&qkvb, g_qkv);
    cudaGetSymbolAddress((void**)&hnH,  g_hnH);
    cudaGetSymbolAddress((void**)&tmpH, g_tmpH);
    cudaGetSymbolAddress((void**)&wH,   g_wH);

    cudaFuncSetAttribute(attn_kernel,
                         cudaFuncAttributeMaxDynamicSharedMemorySize, ATTN_SMEM);
    cudaFuncSetAttribute(mgemm_kernel<false,false,false,false>,
                         cudaFuncAttributeMaxDynamicSharedMemorySize, G_SMEM);
    cudaFuncSetAttribute(mgemm_kernel<false,true,true,false>,
                         cudaFuncAttributeMaxDynamicSharedMemorySize, G_SMEM);
    cudaFuncSetAttribute(mgemm_kernel<true,false,true,true>,
                         cudaFuncAttributeMaxDynamicSharedMemorySize, G_SMEM);

    // preconvert all weights to fp16 (once per launch)
    wconv_kernel<<<(L_ * D3D_ / 8 + 255) / 256, 256>>>(piw,  wH + OFF_PIW, L_ * D3D_ / 8);
    wconv_kernel<<<(L_ * DD_  / 8 + 255) / 256, 256>>>(pow_, wH + OFF_POW, L_ * DD_ / 8);
    wconv_kernel<<<(L_ * FFD_ / 8 + 255) / 256, 256>>>(l1w,  wH + OFF_L1W, L_ * FFD_ / 8);
    wconv_kernel<<<(L_ * DFF_ / 8 + 255) / 256, 256>>>(l2w,  wH + OFF_L2W, L_ * DFF_ / 8);

    embed_kernel<<<ROWS_, 256>>>(x, ew, h);

    for (int l = 0; l < L_; l++) {
        ln_kernel<<<ROWS_ / 8, 256>>>(h, hn, hnH, n1w + l * D_, n1b + l * D_);
        mgemm_kernel<false,false,false,false><<<dim3(6, 512), 256, G_SMEM>>>(
            hnH, wH + OFF_PIW + (size_t)l * D3D_,
            nullptr, nullptr, qkvb, nullptr, ROWS_, 3 * D_, D_);
        attn_kernel<<<dim3(H_, B_), 256, ATTN_SMEM>>>(qkvb, ids, tmpH);
        mgemm_kernel<false,true,true,false><<<dim3(2, 512), 256, G_SMEM>>>(
            tmpH, wH + OFF_POW + (size_t)l * DD_,
            pob + l * D_, hn, h, nullptr, ROWS_, D_, D_);
        ln_kernel<<<ROWS_ / 8, 256>>>(h, hn, hnH, n2w + l * D_, n2b + l * D_);
        mgemm_kernel<true,false,true,true><<<dim3(3, 512), 256, G_SMEM>>>(
            hnH, wH + OFF_L1W + (size_t)l * FFD_,
            l1b + l * FF_, nullptr, nullptr, tmpH, ROWS_, FF_, D_);
        mgemm_kernel<false,true,true,false><<<dim3(2, 512), 256, G_SMEM>>>(
            tmpH, wH + OFF_L2W + (size_t)l * DFF_,
            l2b + l * D_, hn, h, nullptr, ROWS_, D_, FF_);
    }

    logits_kernel<<<B_, 256>>>(h, lw, lb, out);
}

// round 9
// speedup vs baseline: 1.9205x; 1.0371x over previous
#include <cuda_runtime.h>
#include <cuda_fp16.h>
#include <cstdint>
#include <math.h>

// Problem dims
#define B_ 512
#define S_ 128
#define D_ 256
#define H_ 4
#define DH_ 64
#define FF_ 384
#define L_ 6
#define ROWS_ (B_ * S_)
#define SCALE_ 0.125f
#define LOG2E_ 1.4426950408889634f

#define DD_   (D_ * D_)
#define D3D_  (3 * D_ * D_)
#define FFD_  (FF_ * D_)
#define DFF_  (D_ * FF_)
#define OFF_PIW 0
#define OFF_POW (L_ * D3D_)
#define OFF_L1W (OFF_POW + L_ * DD_)
#define OFF_L2W (OFF_L1W + L_ * FFD_)
#define W_TOTAL (OFF_L2W + L_ * DFF_)

// ---------------- scratch (device globals) ----------------------------------
__device__ float g_h  [(size_t)ROWS_ * D_];
__device__ float g_hn [(size_t)ROWS_ * D_];
__device__ __half g_qkvH[(size_t)ROWS_ * 3 * D_];
__device__ __half g_hnH [(size_t)ROWS_ * D_];
__device__ __half g_tmpH[(size_t)ROWS_ * FF_];
__device__ __half g_wH  [W_TOTAL];

extern __shared__ char dyn_smem[];

// ======================= helpers ===========================================
__device__ __forceinline__ uint32_t smem_u32(const void* p) {
    uint32_t a;
    asm("{ .reg .u64 t; cvta.to.shared.u64 t, %1; cvt.u32.u64 %0, t; }"
        : "=r"(a) : "l"(p));
    return a;
}
__device__ __forceinline__ void ldsm4(uint32_t a, uint32_t* r) {
    asm volatile("ldmatrix.sync.aligned.m8n8.x4.shared.b16 {%0,%1,%2,%3}, [%4];"
                 : "=r"(r[0]), "=r"(r[1]), "=r"(r[2]), "=r"(r[3]) : "r"(a));
}
__device__ __forceinline__ void ldsm2(uint32_t a, uint32_t* r) {
    asm volatile("ldmatrix.sync.aligned.m8n8.x2.shared.b16 {%0,%1}, [%2];"
                 : "=r"(r[0]), "=r"(r[1]) : "r"(a));
}
__device__ __forceinline__ void mma16816h(float* d, const uint32_t* a,
                                          const uint32_t* b) {
    asm volatile("mma.sync.aligned.m16n8k16.row.col.f32.f16.f16.f32 "
                 "{%0,%1,%2,%3}, {%4,%5,%6,%7}, {%8,%9}, {%0,%1,%2,%3};"
                 : "+f"(d[0]), "+f"(d[1]), "+f"(d[2]), "+f"(d[3])
                 : "r"(a[0]), "r"(a[1]), "r"(a[2]), "r"(a[3]),
                   "r"(b[0]), "r"(b[1]));
}
__device__ __forceinline__ uint32_t pack2h(float a, float b) {
    __half2 h = __floats2half2_rn(a, b);
    uint32_t r;
    memcpy(&r, &h, 4);
    return r;
}
__device__ __forceinline__ void cp_async16(uint32_t sa, const void* ga) {
    asm volatile("cp.async.cg.shared.global [%0], [%1], 16;"
                 :: "r"(sa), "l"(ga) : "memory");
}
#define CP_COMMIT() asm volatile("cp.async.commit_group;" ::: "memory")
#define CP_WAIT(N)  asm volatile("cp.async.wait_group %0;" :: "n"(N) : "memory")

// ---------------- weight preconversion (fp32 -> fp16) ------------------------
__global__ __launch_bounds__(256) void wconv_kernel(
    const float* __restrict__ src, __half* __restrict__ dst, int n8)
{
    int idx = blockIdx.x * 256 + threadIdx.x;
    if (idx >= n8) return;
    const float* p = src + (size_t)idx * 8;
    float4 v0 = *(const float4*)(p);
    float4 v1 = *(const float4*)(p + 4);
    uint4 o;
    o.x = pack2h(v0.x, v0.y);
    o.y = pack2h(v0.z, v0.w);
    o.z = pack2h(v1.x, v1.y);
    o.w = pack2h(v1.z, v1.w);
    *(uint4*)(dst + (size_t)idx * 8) = o;
}

// ======================= fp16 mma GEMM ======================================
#define GO_BIAS  0u
#define GO_STAGE 1024u
#define STAGE_SZ 32768u
#define G_SMEM   (1024 + 2 * 32768)   // 66560

__device__ __forceinline__ void gemm_issue_chunk(
    uint32_t sb, const __half* A, const __half* W,
    int bm, int bn, int K, int c, int s_row, int s_g, uint32_t s_off)
{
    const int kc = c << 6;
    const uint32_t stage = GO_STAGE + (uint32_t)(c & 1) * STAGE_SZ;
#pragma unroll
    for (int it = 0; it < 4; it++) {
        uint32_t off = s_off + (uint32_t)(it * 32 * 128);
        int row = s_row + it * 32;
        cp_async16(sb + stage + off,
                   A + (size_t)(bm + row) * K + kc + s_g * 8);
        cp_async16(sb + stage + 16384 + off,
                   W + (size_t)(bn + row) * K + kc + s_g * 8);
    }
    CP_COMMIT();
}

template<bool GELU, bool RES, bool HASB, bool OUTH>
__global__ __launch_bounds__(256)
void mgemm_kernel(const __half* __restrict__ A, const __half* __restrict__ W,
                  const float* __restrict__ bias, const float* __restrict__ res,
                  float* __restrict__ Cf, __half* __restrict__ Ch,
                  int M, int N, int K)
{
    char* smem = dyn_smem;
    const uint32_t sb = smem_u32(smem);
    const int tid  = threadIdx.x;
    const int lane = tid & 31;
    const int warp = tid >> 5;
    const int bm = blockIdx.y << 7;
    const int bn = blockIdx.x << 7;
    const int wm = (warp >> 2) << 6;
    const int wn = (warp & 3) << 5;

    float* sbias = (float*)(smem + GO_BIAS);
    if (HASB && tid < 128) sbias[tid] = bias[bn + tid];

    float acc[4][4][4];
#pragma unroll
    for (int i = 0; i < 4; i++)
#pragma unroll
        for (int j = 0; j < 4; j++)
#pragma unroll
            for (int k = 0; k < 4; k++) acc[i][j][k] = 0.0f;

    const int a_row = lane & 15;
    const int a_cg  = lane >> 4;
    const int b_row = lane & 7;
    const int b_cg  = (lane >> 3) & 1;

    const int s_row = tid >> 3;
    const int s_g   = tid & 7;
    const uint32_t s_off =
        (uint32_t)(s_row * 128 + ((s_g ^ (s_row & 7)) << 4));

    const int nch = K >> 6;

    gemm_issue_chunk(sb, A, W, bm, bn, K, 0, s_row, s_g, s_off);
    for (int c = 0; c < nch; c++) {
        if (c + 1 < nch) {
            gemm_issue_chunk(sb, A, W, bm, bn, K, c + 1, s_row, s_g, s_off);
            CP_WAIT(1);
        } else {
            CP_WAIT(0);
        }
        __syncthreads();

        const uint32_t sA = sb + GO_STAGE + (uint32_t)(c & 1) * STAGE_SZ;
        const uint32_t sW = sA + 16384;
#pragma unroll
        for (int ks = 0; ks < 4; ks++) {
            uint32_t ah[4][4], wh[4][2];
#pragma unroll
            for (int mt = 0; mt < 4; mt++) {
                int row = wm + mt * 16 + a_row;
                int cg  = ks * 2 + a_cg;
                ldsm4(sA + row * 128 + ((cg ^ (row & 7)) << 4), ah[mt]);
            }
#pragma unroll
            for (int nt = 0; nt < 4; nt++) {
                int row = wn + nt * 8 + b_row;
                int cg  = ks * 2 + b_cg;
                ldsm2(sW + row * 128 + ((cg ^ (row & 7)) << 4), wh[nt]);
            }
#pragma unroll
            for (int mt = 0; mt < 4; mt++)
#pragma unroll
                for (int nt = 0; nt < 4; nt++)
                    mma16816h(acc[mt][nt], ah[mt], wh[nt]);
        }
        __syncthreads();
    }

    // ---- epilogue ----
#pragma unroll
    for (int mt = 0; mt < 4; mt++) {
        int r = bm + wm + mt * 16 + (lane >> 2);
#pragma unroll
        for (int nt = 0; nt < 4; nt++) {
            int cl = wn + nt * 8 + ((lane & 3) << 1);
            int c  = bn + cl;
            float2 v0 = make_float2(acc[mt][nt][0], acc[mt][nt][1]);
            float2 v1 = make_float2(acc[mt][nt][2], acc[mt][nt][3]);
            if (HASB) {
                float b0 = sbias[cl], b1 = sbias[cl + 1];
                v0.x += b0; v0.y += b1; v1.x += b0; v1.y += b1;
            }
            if (GELU) {
                v0.x = 0.5f * v0.x * (1.0f + erff(v0.x * 0.70710678f));
                v0.y = 0.5f * v0.y * (1.0f + erff(v0.y * 0.70710678f));
                v1.x = 0.5f * v1.x * (1.0f + erff(v1.x * 0.70710678f));
                v1.y = 0.5f * v1.y * (1.0f + erff(v1.y * 0.70710678f));
            }
            size_t i0 = (size_t)r * N + c;
            size_t i1 = (size_t)(r + 8) * N + c;
            if (OUTH) {
                *(uint32_t*)(Ch + i0) = pack2h(v0.x, v0.y);
                *(uint32_t*)(Ch + i1) = pack2h(v1.x, v1.y);
            } else {
                if (RES) {
                    float2 r0 = *(const float2*)(res + i0);
                    float2 r1 = *(const float2*)(res + i1);
                    v0.x += r0.x; v0.y += r0.y; v1.x += r1.x; v1.y += r1.y;
                }
                *(float2*)(Cf + i0) = v0;
                *(float2*)(Cf + i1) = v1;
            }
        }
    }
}

// ---------------- embedding + positional encoding ---------------------------
__global__ __launch_bounds__(256) void embed_kernel(
    const int* __restrict__ x, const float* __restrict__ ew,
    float* __restrict__ h)
{
    int row = blockIdx.x;
    int d   = threadIdx.x;
    int s   = row & (S_ - 1);
    int tok = x[row];
    int p   = d >> 1;
    float dim_t = powf(10000.0f, (float)p * (1.0f / 128.0f));
    float pos   = (float)s / dim_t;
    float pe    = (d & 1) ? cosf(pos) : sinf(pos);
    h[(size_t)row * D_ + d] = ew[(size_t)tok * D_ + d] + pe;
}

// ---------------- LayerNorm + fp16 emit --------------------------------------
__global__ __launch_bounds__(256) void ln_kernel(
    const float* __restrict__ in, float* __restrict__ out,
    __half* __restrict__ outH,
    const float* __restrict__ w, const float* __restrict__ b)
{
    int warp = threadIdx.x >> 5, lane = threadIdx.x & 31;
    size_t row = (size_t)blockIdx.x * 8 + warp;
    const float* p = in + row * D_;
    float4 a0 = *(const float4*)(p + lane * 4);
    float4 a1 = *(const float4*)(p + 128 + lane * 4);
    float s = a0.x + a0.y + a0.z + a0.w + a1.x + a1.y + a1.z + a1.w;
    float q = a0.x*a0.x + a0.y*a0.y + a0.z*a0.z + a0.w*a0.w
            + a1.x*a1.x + a1.y*a1.y + a1.z*a1.z + a1.w*a1.w;
#pragma unroll
    for (int o = 16; o > 0; o >>= 1) {
        s += __shfl_xor_sync(0xffffffffu, s, o);
        q += __shfl_xor_sync(0xffffffffu, q, o);
    }
    float mean = s * (1.0f / 256.0f);
    float var  = q * (1.0f / 256.0f) - mean * mean;
    float rstd = rsqrtf(var + 1e-5f);
    float4 w0 = *(const float4*)(w + lane * 4);
    float4 w1 = *(const float4*)(w + 128 + lane * 4);
    float4 b0 = *(const float4*)(b + lane * 4);
    float4 b1 = *(const float4*)(b + 128 + lane * 4);
    float4 o0, o1;
    o0.x = (a0.x - mean) * rstd * w0.x + b0.x;
    o0.y = (a0.y - mean) * rstd * w0.y + b0.y;
    o0.z = (a0.z - mean) * rstd * w0.z + b0.z;
    o0.w = (a0.w - mean) * rstd * w0.w + b0.w;
    o1.x = (a1.x - mean) * rstd * w1.x + b1.x;
    o1.y = (a1.y - mean) * rstd * w1.y + b1.y;
    o1.z = (a1.z - mean) * rstd * w1.z + b1.z;
    o1.w = (a1.w - mean) * rstd * w1.w + b1.w;
    float* po = out + row * D_;
    *(float4*)(po + lane * 4)       = o0;
    *(float4*)(po + 128 + lane * 4) = o1;
    *(uint2*)(outH + row * D_ + lane * 4) =
        make_uint2(pack2h(o0.x, o0.y), pack2h(o0.z, o0.w));
    *(uint2*)(outH + row * D_ + 128 + lane * 4) =
        make_uint2(pack2h(o1.x, o1.y), pack2h(o1.z, o1.w));
}

// ---------------- attention: fp16 QK (HFMA2) + h2exp2 softmax ---------------
// smem: K fp16 [128][64] (16KB), V fp32 [128][64] (32KB), mask (512B)
#define ATTN_SMEM (16384 + 32768 + 512)   // 49664

__global__ __launch_bounds__(256) void attn_kernel(
    const __half* __restrict__ qkv, const float* __restrict__ ids,
    __half* __restrict__ oh)
{
    char* smem = dyn_smem;
    __half* Kh = (__half*)smem;
    float*  Vs = (float*)(smem + 16384);
    float*  msk = (float*)(smem + 16384 + 32768);
    int h = blockIdx.x, b = blockIdx.y, t = threadIdx.x;
    const __half* base = qkv + (size_t)b * S_ * (3 * D_);
    const int qoff = h * DH_;
    const int koff = D_ + h * DH_;
    const int voff = 2 * D_ + h * DH_;

    // K: 1024 16B groups
    for (int idx = t; idx < 1024; idx += 256) {
        int r = idx >> 3, g = idx & 7;
        *(uint4*)(Kh + r * 64 + g * 8) =
            *(const uint4*)(base + (size_t)r * 768 + koff + g * 8);
    }
    // V: fp16 -> fp32
    for (int idx = t; idx < 2048; idx += 256) {
        int r = idx >> 4, c = (idx & 15) * 4;
        uint2 hv = *(const uint2*)(base + (size_t)r * 768 + voff + c);
        __half2 h0, h1;
        memcpy(&h0, &hv.x, 4); memcpy(&h1, &hv.y, 4);
        float2 f0 = __half22float2(h0), f1 = __half22float2(h1);
        *(float4*)(Vs + r * 64 + c) = make_float4(f0.x, f0.y, f1.x, f1.y);
    }
    if (t < 128) msk[t] = ids[b * S_ + t] * (-1e9f * SCALE_ * LOG2E_);

    const int qr = t >> 1;
    const int hf = t & 1;
    __half2 q[16];
    {
        const __half* qp = base + (size_t)qr * 768 + qoff;
#pragma unroll
        for (int i = 0; i < 4; i++) {
            uint4 v = *(const uint4*)(qp + (2 * i + hf) * 8);
            memcpy(&q[i*4+0], &v.x, 4); memcpy(&q[i*4+1], &v.y, 4);
            memcpy(&q[i*4+2], &v.z, 4); memcpy(&q[i*4+3], &v.w, 4);
        }
    }
    __syncthreads();

    const float kscale = SCALE_ * LOG2E_;
    float m = -1e30f, l = 0.0f;
    float o[32];
#pragma unroll
    for (int i = 0; i < 32; i++) o[i] = 0.0f;

    for (int j0 = 0; j0 < 128; j0 += 16) {
        float s[16];
        float cm = -1e30f;
#pragma unroll
        for (int jj = 0; jj < 16; jj++) {
            const __half* kr = Kh + (j0 + jj) * 64;
            __half2 a0 = __floats2half2_rn(0.f, 0.f);
            __half2 a1 = a0;
#pragma unroll
            for (int i = 0; i < 4; i++) {
                uint4 kv = *(const uint4*)(kr + (2 * i + hf) * 8);
                __half2 k0, k1, k2, k3;
                memcpy(&k0, &kv.x, 4); memcpy(&k1, &kv.y, 4);
                memcpy(&k2, &kv.z, 4); memcpy(&k3, &kv.w, 4);
                a0 = __hfma2(q[i*4+0], k0, a0);
                a1 = __hfma2(q[i*4+1], k1, a1);
                a0 = __hfma2(q[i*4+2], k2, a0);
                a1 = __hfma2(q[i*4+3], k3, a1);
            }
            __half2 asum = __hadd2(a0, a1);
            float dot = __low2float(asum) + __high2float(asum);
            dot += __shfl_xor_sync(0xffffffffu, dot, 1);
            float sc = fmaf(dot, kscale, msk[j0 + jj]);
            s[jj] = sc;
            cm = fmaxf(cm, sc);
        }
        float mn = fmaxf(m, cm);
        float corr = exp2f(m - mn);
        l *= corr;
#pragma unroll
        for (int i = 0; i < 32; i++) o[i] *= corr;
#pragma unroll
        for (int jp = 0; jp < 8; jp++) {
            __half2 d = __floats2half2_rn(s[2*jp] - mn, s[2*jp+1] - mn);
            __half2 ph = h2exp2(d);
            float2 pf = __half22float2(ph);
            l += pf.x + pf.y;
            const float* vr0 = Vs + (j0 + 2*jp) * 64;
            const float* vr1 = vr0 + 64;
#pragma unroll
            for (int i = 0; i < 8; i++) {
                float4 v0 = *(const float4*)(vr0 + (2 * i + hf) * 4);
                float4 v1 = *(const float4*)(vr1 + (2 * i + hf) * 4);
                o[i*4]   = fmaf(pf.x, v0.x, fmaf(pf.y, v1.x, o[i*4]));
                o[i*4+1] = fmaf(pf.x, v0.y, fmaf(pf.y, v1.y, o[i*4+1]));
                o[i*4+2] = fmaf(pf.x, v0.z, fmaf(pf.y, v1.z, o[i*4+2]));
                o[i*4+3] = fmaf(pf.x, v0.w, fmaf(pf.y, v1.w, o[i*4+3]));
            }
        }
        m = mn;
    }
    float inv = 1.0f / l;
    size_t obase = (size_t)(b * S_ + qr) * D_ + h * DH_;
#pragma unroll
    for (int i = 0; i < 8; i++) {
        int gi = 2 * i + hf;
        *(uint2*)(oh + obase + gi * 4) =
            make_uint2(pack2h(o[i*4] * inv,   o[i*4+1] * inv),
                       pack2h(o[i*4+2] * inv, o[i*4+3] * inv));
    }
}

// ---------------- final logits ---------------------------------------------
__global__ __launch_bounds__(256) void logits_kernel(
    const float* __restrict__ hflat, const float* __restrict__ W,
    const float* __restrict__ bias, float* __restrict__ out)
{
    int b = blockIdx.x, t = threadIdx.x;
    const float4* h4  = (const float4*)(hflat + (size_t)b * 32768);
    const float4* w04 = (const float4*)(W);
    const float4* w14 = (const float4*)(W + 32768);
    float a0 = 0.0f, a1 = 0.0f;
    for (int i = t; i < 8192; i += 256) {
        float4 x = h4[i], u = w04[i], v = w14[i];
        a0 += x.x*u.x + x.y*u.y + x.z*u.z + x.w*u.w;
        a1 += x.x*v.x + x.y*v.y + x.z*v.z + x.w*v.w;
    }
    __shared__ float r0[256], r1[256];
    r0[t] = a0; r1[t] = a1;
    __syncthreads();
    for (int s = 128; s > 0; s >>= 1) {
        if (t < s) { r0[t] += r0[t + s]; r1[t] += r1[t + s]; }
        __syncthreads();
    }
    if (t == 0) {
        out[b * 2 + 0] = r0[0] + bias[0];
        out[b * 2 + 1] = r1[0] + bias[1];
    }
}

// ---------------- launch ----------------------------------------------------
extern "C" void kernel_launch(void* const* d_in, const int* in_sizes, int n_in,
                              void* d_out, int out_size)
{
    const int*   x    = (const int*)  d_in[0];
    const float* ids  = (const float*)d_in[1];
    const float* ew   = (const float*)d_in[2];
    const float* n1w  = (const float*)d_in[3];
    const float* n1b  = (const float*)d_in[4];
    const float* piw  = (const float*)d_in[5];
    const float* pow_ = (const float*)d_in[6];
    const float* pob  = (const float*)d_in[7];
    const float* n2w  = (const float*)d_in[8];
    const float* n2b  = (const float*)d_in[9];
    const float* l1w  = (const float*)d_in[10];
    const float* l1b  = (const float*)d_in[11];
    const float* l2w  = (const float*)d_in[12];
    const float* l2b  = (const float*)d_in[13];
    const float* lw   = (const float*)d_in[14];
    const float* lb   = (const float*)d_in[15];
    float* out = (float*)d_out;

    float *h, *hn;
    __half *qkvh, *hnH, *tmpH, *wH;
    cudaGetSymbolAddress((void**)&h,    g_h);
    cudaGetSymbolAddress((void**)&hn,   g_hn);
    cudaGetSymbolAddress((void**)&qkvh, g_qkvH);
    cudaGetSymbolAddress((void**)&hnH,  g_hnH);
    cudaGetSymbolAddress((void**)&tmpH, g_tmpH);
    cudaGetSymbolAddress((void**)&wH,   g_wH);

    cudaFuncSetAttribute(attn_kernel,
                         cudaFuncAttributeMaxDynamicSharedMemorySize, ATTN_SMEM);
    cudaFuncSetAttribute(mgemm_kernel<false,false,false,true>,
                         cudaFuncAttributeMaxDynamicSharedMemorySize, G_SMEM);
    cudaFuncSetAttribute(mgemm_kernel<false,true,true,false>,
                         cudaFuncAttributeMaxDynamicSharedMemorySize, G_SMEM);
    cudaFuncSetAttribute(mgemm_kernel<true,false,true,true>,
                         cudaFuncAttributeMaxDynamicSharedMemorySize, G_SMEM);

    // preconvert all weights to fp16 (once per launch)
    wconv_kernel<<<(L_ * D3D_ / 8 + 255) / 256, 256>>>(piw,  wH + OFF_PIW, L_ * D3D_ / 8);
    wconv_kernel<<<(L_ * DD_  / 8 + 255) / 256, 256>>>(pow_, wH + OFF_POW, L_ * DD_ / 8);
    wconv_kernel<<<(L_ * FFD_ / 8 + 255) / 256, 256>>>(l1w,  wH + OFF_L1W, L_ * FFD_ / 8);
    wconv_kernel<<<(L_ * DFF_ / 8 + 255) / 256, 256>>>(l2w,  wH + OFF_L2W, L_ * DFF_ / 8);

    embed_kernel<<<ROWS_, 256>>>(x, ew, h);

    for (int l = 0; l < L_; l++) {
        ln_kernel<<<ROWS_ / 8, 256>>>(h, hn, hnH, n1w + l * D_, n1b + l * D_);
        // qkv (fp16 out)
        mgemm_kernel<false,false,false,true><<<dim3(6, 512), 256, G_SMEM>>>(
            hnH, wH + OFF_PIW + (size_t)l * D3D_,
            nullptr, nullptr, nullptr, qkvh, ROWS_, 3 * D_, D_);
        attn_kernel<<<dim3(H_, B_), 256, ATTN_SMEM>>>(qkvh, ids, tmpH);
        mgemm_kernel<false,true,true,false><<<dim3(2, 512), 256, G_SMEM>>>(
            tmpH, wH + OFF_POW + (size_t)l * DD_,
            pob + l * D_, hn, h, nullptr, ROWS_, D_, D_);
        ln_kernel<<<ROWS_ / 8, 256>>>(h, hn, hnH, n2w + l * D_, n2b + l * D_);
        mgemm_kernel<true,false,true,true><<<dim3(3, 512), 256, G_SMEM>>>(
            hnH, wH + OFF_L1W + (size_t)l * FFD_,
            l1b + l * FF_, nullptr, nullptr, tmpH, ROWS_, FF_, D_);
        mgemm_kernel<false,true,true,false><<<dim3(2, 512), 256, G_SMEM>>>(
            tmpH, wH + OFF_L2W + (size_t)l * DFF_,
            l2b + l * D_, hn, h, nullptr, ROWS_, D_, FF_);
    }

    logits_kernel<<<B_, 256>>>(h, lw, lb, out);
}

// round 10
// speedup vs baseline: 2.7773x; 1.4461x over previous
#include <cuda_runtime.h>
#include <cuda_fp16.h>
#include <cstdint>
#include <math.h>

// Problem dims
#define B_ 512
#define S_ 128
#define D_ 256
#define H_ 4
#define DH_ 64
#define FF_ 384
#define L_ 6
#define ROWS_ (B_ * S_)
#define SCALE_ 0.125f
#define LOG2E_ 1.4426950408889634f

#define DD_   (D_ * D_)
#define D3D_  (3 * D_ * D_)
#define FFD_  (FF_ * D_)
#define DFF_  (D_ * FF_)
#define OFF_PIW 0
#define OFF_POW (L_ * D3D_)
#define OFF_L1W (OFF_POW + L_ * DD_)
#define OFF_L2W (OFF_L1W + L_ * FFD_)
#define W_TOTAL (OFF_L2W + L_ * DFF_)

// ---------------- scratch (device globals) ----------------------------------
__device__ float g_h  [(size_t)ROWS_ * D_];
__device__ float g_hn [(size_t)ROWS_ * D_];
__device__ __half g_qkvH[(size_t)ROWS_ * 3 * D_];
__device__ __half g_hnH [(size_t)ROWS_ * D_];
__device__ __half g_tmpH[(size_t)ROWS_ * FF_];
__device__ __half g_wH  [W_TOTAL];

extern __shared__ char dyn_smem[];

// ======================= helpers ===========================================
__device__ __forceinline__ uint32_t smem_u32(const void* p) {
    uint32_t a;
    asm("{ .reg .u64 t; cvta.to.shared.u64 t, %1; cvt.u32.u64 %0, t; }"
        : "=r"(a) : "l"(p));
    return a;
}
__device__ __forceinline__ void ldsm4(uint32_t a, uint32_t* r) {
    asm volatile("ldmatrix.sync.aligned.m8n8.x4.shared.b16 {%0,%1,%2,%3}, [%4];"
                 : "=r"(r[0]), "=r"(r[1]), "=r"(r[2]), "=r"(r[3]) : "r"(a));
}
__device__ __forceinline__ void ldsm2(uint32_t a, uint32_t* r) {
    asm volatile("ldmatrix.sync.aligned.m8n8.x2.shared.b16 {%0,%1}, [%2];"
                 : "=r"(r[0]), "=r"(r[1]) : "r"(a));
}
__device__ __forceinline__ void ldsm2t(uint32_t a, uint32_t* r) {
    asm volatile("ldmatrix.sync.aligned.m8n8.x2.trans.shared.b16 {%0,%1}, [%2];"
                 : "=r"(r[0]), "=r"(r[1]) : "r"(a));
}
__device__ __forceinline__ void mma16816h(float* d, const uint32_t* a,
                                          const uint32_t* b) {
    asm volatile("mma.sync.aligned.m16n8k16.row.col.f32.f16.f16.f32 "
                 "{%0,%1,%2,%3}, {%4,%5,%6,%7}, {%8,%9}, {%0,%1,%2,%3};"
                 : "+f"(d[0]), "+f"(d[1]), "+f"(d[2]), "+f"(d[3])
                 : "r"(a[0]), "r"(a[1]), "r"(a[2]), "r"(a[3]),
                   "r"(b[0]), "r"(b[1]));
}
__device__ __forceinline__ uint32_t pack2h(float a, float b) {
    __half2 h = __floats2half2_rn(a, b);
    uint32_t r;
    memcpy(&r, &h, 4);
    return r;
}
__device__ __forceinline__ void cp_async16(uint32_t sa, const void* ga) {
    asm volatile("cp.async.cg.shared.global [%0], [%1], 16;"
                 :: "r"(sa), "l"(ga) : "memory");
}
#define CP_COMMIT() asm volatile("cp.async.commit_group;" ::: "memory")
#define CP_WAIT(N)  asm volatile("cp.async.wait_group %0;" :: "n"(N) : "memory")

// ---------------- weight preconversion (fp32 -> fp16) ------------------------
__global__ __launch_bounds__(256) void wconv_kernel(
    const float* __restrict__ src, __half* __restrict__ dst, int n8)
{
    int idx = blockIdx.x * 256 + threadIdx.x;
    if (idx >= n8) return;
    const float* p = src + (size_t)idx * 8;
    float4 v0 = *(const float4*)(p);
    float4 v1 = *(const float4*)(p + 4);
    uint4 o;
    o.x = pack2h(v0.x, v0.y);
    o.y = pack2h(v0.z, v0.w);
    o.z = pack2h(v1.x, v1.y);
    o.w = pack2h(v1.z, v1.w);
    *(uint4*)(dst + (size_t)idx * 8) = o;
}

// ======================= fp16 mma GEMM ======================================
#define GO_BIAS  0u
#define GO_STAGE 1024u
#define STAGE_SZ 32768u
#define G_SMEM   (1024 + 2 * 32768)   // 66560

__device__ __forceinline__ void gemm_issue_chunk(
    uint32_t sb, const __half* A, const __half* W,
    int bm, int bn, int K, int c, int s_row, int s_g, uint32_t s_off)
{
    const int kc = c << 6;
    const uint32_t stage = GO_STAGE + (uint32_t)(c & 1) * STAGE_SZ;
#pragma unroll
    for (int it = 0; it < 4; it++) {
        uint32_t off = s_off + (uint32_t)(it * 32 * 128);
        int row = s_row + it * 32;
        cp_async16(sb + stage + off,
                   A + (size_t)(bm + row) * K + kc + s_g * 8);
        cp_async16(sb + stage + 16384 + off,
                   W + (size_t)(bn + row) * K + kc + s_g * 8);
    }
    CP_COMMIT();
}

template<bool GELU, bool RES, bool HASB, bool OUTH>
__global__ __launch_bounds__(256)
void mgemm_kernel(const __half* __restrict__ A, const __half* __restrict__ W,
                  const float* __restrict__ bias, const float* __restrict__ res,
                  float* __restrict__ Cf, __half* __restrict__ Ch,
                  int M, int N, int K)
{
    char* smem = dyn_smem;
    const uint32_t sb = smem_u32(smem);
    const int tid  = threadIdx.x;
    const int lane = tid & 31;
    const int warp = tid >> 5;
    const int bm = blockIdx.y << 7;
    const int bn = blockIdx.x << 7;
    const int wm = (warp >> 2) << 6;
    const int wn = (warp & 3) << 5;

    float* sbias = (float*)(smem + GO_BIAS);
    if (HASB && tid < 128) sbias[tid] = bias[bn + tid];

    float acc[4][4][4];
#pragma unroll
    for (int i = 0; i < 4; i++)
#pragma unroll
        for (int j = 0; j < 4; j++)
#pragma unroll
            for (int k = 0; k < 4; k++) acc[i][j][k] = 0.0f;

    const int a_row = lane & 15;
    const int a_cg  = lane >> 4;
    const int b_row = lane & 7;
    const int b_cg  = (lane >> 3) & 1;

    const int s_row = tid >> 3;
    const int s_g   = tid & 7;
    const uint32_t s_off =
        (uint32_t)(s_row * 128 + ((s_g ^ (s_row & 7)) << 4));

    const int nch = K >> 6;

    gemm_issue_chunk(sb, A, W, bm, bn, K, 0, s_row, s_g, s_off);
    for (int c = 0; c < nch; c++) {
        if (c + 1 < nch) {
            gemm_issue_chunk(sb, A, W, bm, bn, K, c + 1, s_row, s_g, s_off);
            CP_WAIT(1);
        } else {
            CP_WAIT(0);
        }
        __syncthreads();

        const uint32_t sA = sb + GO_STAGE + (uint32_t)(c & 1) * STAGE_SZ;
        const uint32_t sW = sA + 16384;
#pragma unroll
        for (int ks = 0; ks < 4; ks++) {
            uint32_t ah[4][4], wh[4][2];
#pragma unroll
            for (int mt = 0; mt < 4; mt++) {
                int row = wm + mt * 16 + a_row;
                int cg  = ks * 2 + a_cg;
                ldsm4(sA + row * 128 + ((cg ^ (row & 7)) << 4), ah[mt]);
            }
#pragma unroll
            for (int nt = 0; nt < 4; nt++) {
                int row = wn + nt * 8 + b_row;
                int cg  = ks * 2 + b_cg;
                ldsm2(sW + row * 128 + ((cg ^ (row & 7)) << 4), wh[nt]);
            }
#pragma unroll
            for (int mt = 0; mt < 4; mt++)
#pragma unroll
                for (int nt = 0; nt < 4; nt++)
                    mma16816h(acc[mt][nt], ah[mt], wh[nt]);
        }
        __syncthreads();
    }

    // ---- epilogue ----
#pragma unroll
    for (int mt = 0; mt < 4; mt++) {
        int r = bm + wm + mt * 16 + (lane >> 2);
#pragma unroll
        for (int nt = 0; nt < 4; nt++) {
            int cl = wn + nt * 8 + ((lane & 3) << 1);
            int c  = bn + cl;
            float2 v0 = make_float2(acc[mt][nt][0], acc[mt][nt][1]);
            float2 v1 = make_float2(acc[mt][nt][2], acc[mt][nt][3]);
            if (HASB) {
                float b0 = sbias[cl], b1 = sbias[cl + 1];
                v0.x += b0; v0.y += b1; v1.x += b0; v1.y += b1;
            }
            if (GELU) {
                v0.x = 0.5f * v0.x * (1.0f + erff(v0.x * 0.70710678f));
                v0.y = 0.5f * v0.y * (1.0f + erff(v0.y * 0.70710678f));
                v1.x = 0.5f * v1.x * (1.0f + erff(v1.x * 0.70710678f));
                v1.y = 0.5f * v1.y * (1.0f + erff(v1.y * 0.70710678f));
            }
            size_t i0 = (size_t)r * N + c;
            size_t i1 = (size_t)(r + 8) * N + c;
            if (OUTH) {
                *(uint32_t*)(Ch + i0) = pack2h(v0.x, v0.y);
                *(uint32_t*)(Ch + i1) = pack2h(v1.x, v1.y);
            } else {
                if (RES) {
                    float2 r0 = *(const float2*)(res + i0);
                    float2 r1 = *(const float2*)(res + i1);
                    v0.x += r0.x; v0.y += r0.y; v1.x += r1.x; v1.y += r1.y;
                }
                *(float2*)(Cf + i0) = v0;
                *(float2*)(Cf + i1) = v1;
            }
        }
    }
}

// ---------------- embedding + positional encoding ---------------------------
__global__ __launch_bounds__(256) void embed_kernel(
    const int* __restrict__ x, const float* __restrict__ ew,
    float* __restrict__ h)
{
    int row = blockIdx.x;
    int d   = threadIdx.x;
    int s   = row & (S_ - 1);
    int tok = x[row];
    int p   = d >> 1;
    float dim_t = powf(10000.0f, (float)p * (1.0f / 128.0f));
    float pos   = (float)s / dim_t;
    float pe    = (d & 1) ? cosf(pos) : sinf(pos);
    h[(size_t)row * D_ + d] = ew[(size_t)tok * D_ + d] + pe;
}

// ---------------- LayerNorm + fp16 emit --------------------------------------
__global__ __launch_bounds__(256) void ln_kernel(
    const float* __restrict__ in, float* __restrict__ out,
    __half* __restrict__ outH,
    const float* __restrict__ w, const float* __restrict__ b)
{
    int warp = threadIdx.x >> 5, lane = threadIdx.x & 31;
    size_t row = (size_t)blockIdx.x * 8 + warp;
    const float* p = in + row * D_;
    float4 a0 = *(const float4*)(p + lane * 4);
    float4 a1 = *(const float4*)(p + 128 + lane * 4);
    float s = a0.x + a0.y + a0.z + a0.w + a1.x + a1.y + a1.z + a1.w;
    float q = a0.x*a0.x + a0.y*a0.y + a0.z*a0.z + a0.w*a0.w
            + a1.x*a1.x + a1.y*a1.y + a1.z*a1.z + a1.w*a1.w;
#pragma unroll
    for (int o = 16; o > 0; o >>= 1) {
        s += __shfl_xor_sync(0xffffffffu, s, o);
        q += __shfl_xor_sync(0xffffffffu, q, o);
    }
    float mean = s * (1.0f / 256.0f);
    float var  = q * (1.0f / 256.0f) - mean * mean;
    float rstd = rsqrtf(var + 1e-5f);
    float4 w0 = *(const float4*)(w + lane * 4);
    float4 w1 = *(const float4*)(w + 128 + lane * 4);
    float4 b0 = *(const float4*)(b + lane * 4);
    float4 b1 = *(const float4*)(b + 128 + lane * 4);
    float4 o0, o1;
    o0.x = (a0.x - mean) * rstd * w0.x + b0.x;
    o0.y = (a0.y - mean) * rstd * w0.y + b0.y;
    o0.z = (a0.z - mean) * rstd * w0.z + b0.z;
    o0.w = (a0.w - mean) * rstd * w0.w + b0.w;
    o1.x = (a1.x - mean) * rstd * w1.x + b1.x;
    o1.y = (a1.y - mean) * rstd * w1.y + b1.y;
    o1.z = (a1.z - mean) * rstd * w1.z + b1.z;
    o1.w = (a1.w - mean) * rstd * w1.w + b1.w;
    float* po = out + row * D_;
    *(float4*)(po + lane * 4)       = o0;
    *(float4*)(po + 128 + lane * 4) = o1;
    *(uint2*)(outH + row * D_ + lane * 4) =
        make_uint2(pack2h(o0.x, o0.y), pack2h(o0.z, o0.w));
    *(uint2*)(outH + row * D_ + 128 + lane * 4) =
        make_uint2(pack2h(o1.x, o1.y), pack2h(o1.z, o1.w));
}

// ---------------- attention: tensor-core FA (mma QK + PV) --------------------
// CTA = (head, batch). 8 warps; warp owns 16 query rows. Q,K,V fp16 in
// swizzled smem. Scores/probs/output live entirely in registers.
#define ATTN_SMEM (3 * 16384 + 512)   // 49664

__global__ __launch_bounds__(256) void attn_kernel(
    const __half* __restrict__ qkv, const float* __restrict__ ids,
    __half* __restrict__ oh)
{
    char* smem = dyn_smem;
    const uint32_t sb = smem_u32(smem);
    const uint32_t sQ = sb;
    const uint32_t sK = sb + 16384;
    const uint32_t sV = sb + 32768;
    float* msk = (float*)(smem + 49152);
    const int h = blockIdx.x, b = blockIdx.y, t = threadIdx.x;
    const int lane = t & 31, warp = t >> 5;
    const __half* base = qkv + (size_t)b * S_ * 768 + h * DH_;

    // load Q,K,V tiles (1024 16B-groups each) with XOR swizzle
    for (int idx = t; idx < 1024; idx += 256) {
        int r = idx >> 3, g = idx & 7;
        uint32_t off = (uint32_t)(r * 128 + ((g ^ (r & 7)) << 4));
        const __half* src = base + (size_t)r * 768 + g * 8;
        *(uint4*)(smem + off)         = *(const uint4*)(src);        // Q
        *(uint4*)(smem + 16384 + off) = *(const uint4*)(src + 256);  // K
        *(uint4*)(smem + 32768 + off) = *(const uint4*)(src + 512);  // V
    }
    if (t < 128) msk[t] = ids[b * S_ + t] * (-1e9f * SCALE_ * LOG2E_);
    __syncthreads();

    // ---- S = Q K^T  (warp tile 16x128, fp32 accum) ----
    float sacc[16][4];
#pragma unroll
    for (int nt = 0; nt < 16; nt++)
#pragma unroll
        for (int k = 0; k < 4; k++) sacc[nt][k] = 0.0f;

    const int mrow0 = warp * 16;
#pragma unroll
    for (int ks = 0; ks < 4; ks++) {
        uint32_t a[4];
        {
            int row = mrow0 + (lane & 15);
            int cg  = ks * 2 + (lane >> 4);
            ldsm4(sQ + row * 128 + ((cg ^ (row & 7)) << 4), a);
        }
#pragma unroll
        for (int nt = 0; nt < 16; nt++) {
            uint32_t bf[2];
            int row = nt * 8 + (lane & 7);
            int cg  = ks * 2 + ((lane >> 3) & 1);
            ldsm2(sK + row * 128 + ((cg ^ (row & 7)) << 4), bf);
            mma16816h(sacc[nt], a, bf);
        }
    }

    // ---- softmax in registers ----
    const float kscale = SCALE_ * LOG2E_;
    float m0 = -1e30f, m1 = -1e30f;
    const int cq = (lane & 3) * 2;
#pragma unroll
    for (int nt = 0; nt < 16; nt++) {
        float2 mk = *(float2*)(msk + nt * 8 + cq);
        sacc[nt][0] = fmaf(sacc[nt][0], kscale, mk.x);
        sacc[nt][1] = fmaf(sacc[nt][1], kscale, mk.y);
        sacc[nt][2] = fmaf(sacc[nt][2], kscale, mk.x);
        sacc[nt][3] = fmaf(sacc[nt][3], kscale, mk.y);
        m0 = fmaxf(m0, fmaxf(sacc[nt][0], sacc[nt][1]));
        m1 = fmaxf(m1, fmaxf(sacc[nt][2], sacc[nt][3]));
    }
    m0 = fmaxf(m0, __shfl_xor_sync(0xffffffffu, m0, 1));
    m0 = fmaxf(m0, __shfl_xor_sync(0xffffffffu, m0, 2));
    m1 = fmaxf(m1, __shfl_xor_sync(0xffffffffu, m1, 1));
    m1 = fmaxf(m1, __shfl_xor_sync(0xffffffffu, m1, 2));

    float l0 = 0.0f, l1 = 0.0f;
    uint32_t pa[16], pb[16];
#pragma unroll
    for (int nt = 0; nt < 16; nt++) {
        __half2 d0 = __floats2half2_rn(sacc[nt][0] - m0, sacc[nt][1] - m0);
        __half2 p0 = h2exp2(d0);
        float2 f0 = __half22float2(p0);
        l0 += f0.x + f0.y;
        memcpy(&pa[nt], &p0, 4);
        __half2 d1 = __floats2half2_rn(sacc[nt][2] - m1, sacc[nt][3] - m1);
        __half2 p1 = h2exp2(d1);
        float2 f1 = __half22float2(p1);
        l1 += f1.x + f1.y;
        memcpy(&pb[nt], &p1, 4);
    }
    l0 += __shfl_xor_sync(0xffffffffu, l0, 1);
    l0 += __shfl_xor_sync(0xffffffffu, l0, 2);
    l1 += __shfl_xor_sync(0xffffffffu, l1, 1);
    l1 += __shfl_xor_sync(0xffffffffu, l1, 2);
    float inv0 = 1.0f / l0, inv1 = 1.0f / l1;

    // ---- O = P V  (warp tile 16x64, K=128 over probs) ----
    float oacc[8][4];
#pragma unroll
    for (int vt = 0; vt < 8; vt++)
#pragma unroll
        for (int k = 0; k < 4; k++) oacc[vt][k] = 0.0f;

#pragma unroll
    for (int kk = 0; kk < 8; kk++) {
        uint32_t a[4] = {pa[2 * kk], pb[2 * kk], pa[2 * kk + 1], pb[2 * kk + 1]};
        int row = kk * 16 + (lane & 15);
        uint32_t rbase = sV + row * 128;
        uint32_t rsw = (row & 7) << 4;
#pragma unroll
        for (int vt = 0; vt < 8; vt++) {
            uint32_t bf[2];
            ldsm2t(rbase + (((uint32_t)vt << 4) ^ rsw), bf);
            mma16816h(oacc[vt], a, bf);
        }
    }

    // ---- store O (fp16, scaled by 1/l) ----
    size_t rbase = (size_t)(b * S_ + mrow0 + (lane >> 2)) * D_ + h * DH_;
#pragma unroll
    for (int vt = 0; vt < 8; vt++) {
        int col = vt * 8 + cq;
        *(uint32_t*)(oh + rbase + col) =
            pack2h(oacc[vt][0] * inv0, oacc[vt][1] * inv0);
        *(uint32_t*)(oh + rbase + (size_t)8 * D_ + col) =
            pack2h(oacc[vt][2] * inv1, oacc[vt][3] * inv1);
    }
}

// ---------------- final logits ---------------------------------------------
__global__ __launch_bounds__(256) void logits_kernel(
    const float* __restrict__ hflat, const float* __restrict__ W,
    const float* __restrict__ bias, float* __restrict__ out)
{
    int b = blockIdx.x, t = threadIdx.x;
    const float4* h4  = (const float4*)(hflat + (size_t)b * 32768);
    const float4* w04 = (const float4*)(W);
    const float4* w14 = (const float4*)(W + 32768);
    float a0 = 0.0f, a1 = 0.0f;
    for (int i = t; i < 8192; i += 256) {
        float4 x = h4[i], u = w04[i], v = w14[i];
        a0 += x.x*u.x + x.y*u.y + x.z*u.z + x.w*u.w;
        a1 += x.x*v.x + x.y*v.y + x.z*v.z + x.w*v.w;
    }
    __shared__ float r0[256], r1[256];
    r0[t] = a0; r1[t] = a1;
    __syncthreads();
    for (int s = 128; s > 0; s >>= 1) {
        if (t < s) { r0[t] += r0[t + s]; r1[t] += r1[t + s]; }
        __syncthreads();
    }
    if (t == 0) {
        out[b * 2 + 0] = r0[0] + bias[0];
        out[b * 2 + 1] = r1[0] + bias[1];
    }
}

// ---------------- launch ----------------------------------------------------
extern "C" void kernel_launch(void* const* d_in, const int* in_sizes, int n_in,
                              void* d_out, int out_size)
{
    const int*   x    = (const int*)  d_in[0];
    const float* ids  = (const float*)d_in[1];
    const float* ew   = (const float*)d_in[2];
    const float* n1w  = (const float*)d_in[3];
    const float* n1b  = (const float*)d_in[4];
    const float* piw  = (const float*)d_in[5];
    const float* pow_ = (const float*)d_in[6];
    const float* pob  = (const float*)d_in[7];
    const float* n2w  = (const float*)d_in[8];
    const float* n2b  = (const float*)d_in[9];
    const float* l1w  = (const float*)d_in[10];
    const float* l1b  = (const float*)d_in[11];
    const float* l2w  = (const float*)d_in[12];
    const float* l2b  = (const float*)d_in[13];
    const float* lw   = (const float*)d_in[14];
    const float* lb   = (const float*)d_in[15];
    float* out = (float*)d_out;

    float *h, *hn;
    __half *qkvh, *hnH, *tmpH, *wH;
    cudaGetSymbolAddress((void**)&h,    g_h);
    cudaGetSymbolAddress((void**)&hn,   g_hn);
    cudaGetSymbolAddress((void**)&qkvh, g_qkvH);
    cudaGetSymbolAddress((void**)&hnH,  g_hnH);
    cudaGetSymbolAddress((void**)&tmpH, g_tmpH);
    cudaGetSymbolAddress((void**)&wH,   g_wH);

    cudaFuncSetAttribute(attn_kernel,
                         cudaFuncAttributeMaxDynamicSharedMemorySize, ATTN_SMEM);
    cudaFuncSetAttribute(mgemm_kernel<false,false,false,true>,
                         cudaFuncAttributeMaxDynamicSharedMemorySize, G_SMEM);
    cudaFuncSetAttribute(mgemm_kernel<false,true,true,false>,
                         cudaFuncAttributeMaxDynamicSharedMemorySize, G_SMEM);
    cudaFuncSetAttribute(mgemm_kernel<true,false,true,true>,
                         cudaFuncAttributeMaxDynamicSharedMemorySize, G_SMEM);

    // preconvert all weights to fp16 (once per launch)
    wconv_kernel<<<(L_ * D3D_ / 8 + 255) / 256, 256>>>(piw,  wH + OFF_PIW, L_ * D3D_ / 8);
    wconv_kernel<<<(L_ * DD_  / 8 + 255) / 256, 256>>>(pow_, wH + OFF_POW, L_ * DD_ / 8);
    wconv_kernel<<<(L_ * FFD_ / 8 + 255) / 256, 256>>>(l1w,  wH + OFF_L1W, L_ * FFD_ / 8);
    wconv_kernel<<<(L_ * DFF_ / 8 + 255) / 256, 256>>>(l2w,  wH + OFF_L2W, L_ * DFF_ / 8);

    embed_kernel<<<ROWS_, 256>>>(x, ew, h);

    for (int l = 0; l < L_; l++) {
        ln_kernel<<<ROWS_ / 8, 256>>>(h, hn, hnH, n1w + l * D_, n1b + l * D_);
        // qkv (fp16 out)
        mgemm_kernel<false,false,false,true><<<dim3(6, 512), 256, G_SMEM>>>(
            hnH, wH + OFF_PIW + (size_t)l * D3D_,
            nullptr, nullptr, nullptr, qkvh, ROWS_, 3 * D_, D_);
        attn_kernel<<<dim3(H_, B_), 256, ATTN_SMEM>>>(qkvh, ids, tmpH);
        mgemm_kernel<false,true,true,false><<<dim3(2, 512), 256, G_SMEM>>>(
            tmpH, wH + OFF_POW + (size_t)l * DD_,
            pob + l * D_, hn, h, nullptr, ROWS_, D_, D_);
        ln_kernel<<<ROWS_ / 8, 256>>>(h, hn, hnH, n2w + l * D_, n2b + l * D_);
        mgemm_kernel<true,false,true,true><<<dim3(3, 512), 256, G_SMEM>>>(
            hnH, wH + OFF_L1W + (size_t)l * FFD_,
            l1b + l * FF_, nullptr, nullptr, tmpH, ROWS_, FF_, D_);
        mgemm_kernel<false,true,true,false><<<dim3(2, 512), 256, G_SMEM>>>(
            tmpH, wH + OFF_L2W + (size_t)l * DFF_,
            l2b + l * D_, hn, h, nullptr, ROWS_, D_, FF_);
    }

    logits_kernel<<<B_, 256>>>(h, lw, lb, out);
}

// round 12
// speedup vs baseline: 3.2195x; 1.1592x over previous
#include <cuda_runtime.h>
#include <cuda_fp16.h>
#include <cstdint>
#include <math.h>

// Problem dims
#define B_ 512
#define S_ 128
#define D_ 256
#define H_ 4
#define DH_ 64
#define FF_ 384
#define L_ 6
#define ROWS_ (B_ * S_)
#define SCALE_ 0.125f
#define LOG2E_ 1.4426950408889634f

#define DD_   (D_ * D_)
#define D3D_  (3 * D_ * D_)
#define FFD_  (FF_ * D_)
#define DFF_  (D_ * FF_)
#define OFF_PIW 0
#define OFF_POW (L_ * D3D_)
#define OFF_L1W (OFF_POW + L_ * DD_)
#define OFF_L2W (OFF_L1W + L_ * FFD_)
#define W_TOTAL (OFF_L2W + L_ * DFF_)

// ---------------- scratch (device globals) ----------------------------------
__device__ float g_h  [(size_t)ROWS_ * D_];
__device__ float g_hn [(size_t)ROWS_ * D_];
__device__ __half g_qkvH[(size_t)ROWS_ * 3 * D_];
__device__ __half g_hnH [(size_t)ROWS_ * D_];
__device__ __half g_tmpH[(size_t)ROWS_ * FF_];
__device__ __half g_wH  [W_TOTAL];

extern __shared__ char dyn_smem[];

// ======================= helpers ===========================================
__device__ __forceinline__ uint32_t smem_u32(const void* p) {
    uint32_t a;
    asm("{ .reg .u64 t; cvta.to.shared.u64 t, %1; cvt.u32.u64 %0, t; }"
        : "=r"(a) : "l"(p));
    return a;
}
__device__ __forceinline__ void ldsm4(uint32_t a, uint32_t* r) {
    asm volatile("ldmatrix.sync.aligned.m8n8.x4.shared.b16 {%0,%1,%2,%3}, [%4];"
                 : "=r"(r[0]), "=r"(r[1]), "=r"(r[2]), "=r"(r[3]) : "r"(a));
}
__device__ __forceinline__ void ldsm2(uint32_t a, uint32_t* r) {
    asm volatile("ldmatrix.sync.aligned.m8n8.x2.shared.b16 {%0,%1}, [%2];"
                 : "=r"(r[0]), "=r"(r[1]) : "r"(a));
}
__device__ __forceinline__ void ldsm2t(uint32_t a, uint32_t* r) {
    asm volatile("ldmatrix.sync.aligned.m8n8.x2.trans.shared.b16 {%0,%1}, [%2];"
                 : "=r"(r[0]), "=r"(r[1]) : "r"(a));
}
__device__ __forceinline__ void mma16816h(float* d, const uint32_t* a,
                                          const uint32_t* b) {
    asm volatile("mma.sync.aligned.m16n8k16.row.col.f32.f16.f16.f32 "
                 "{%0,%1,%2,%3}, {%4,%5,%6,%7}, {%8,%9}, {%0,%1,%2,%3};"
                 : "+f"(d[0]), "+f"(d[1]), "+f"(d[2]), "+f"(d[3])
                 : "r"(a[0]), "r"(a[1]), "r"(a[2]), "r"(a[3]),
                   "r"(b[0]), "r"(b[1]));
}
__device__ __forceinline__ uint32_t pack2h(float a, float b) {
    __half2 h = __floats2half2_rn(a, b);
    uint32_t r;
    memcpy(&r, &h, 4);
    return r;
}
__device__ __forceinline__ void cp_async16(uint32_t sa, const void* ga) {
    asm volatile("cp.async.cg.shared.global [%0], [%1], 16;"
                 :: "r"(sa), "l"(ga) : "memory");
}
#define CP_COMMIT() asm volatile("cp.async.commit_group;" ::: "memory")
#define CP_WAIT(N)  asm volatile("cp.async.wait_group %0;" :: "n"(N) : "memory")

// ---------------- weight preconversion (fp32 -> fp16) ------------------------
__global__ __launch_bounds__(256) void wconv_kernel(
    const float* __restrict__ src, __half* __restrict__ dst, int n8)
{
    int idx = blockIdx.x * 256 + threadIdx.x;
    if (idx >= n8) return;
    const float* p = src + (size_t)idx * 8;
    float4 v0 = *(const float4*)(p);
    float4 v1 = *(const float4*)(p + 4);
    uint4 o;
    o.x = pack2h(v0.x, v0.y);
    o.y = pack2h(v0.z, v0.w);
    o.z = pack2h(v1.x, v1.y);
    o.w = pack2h(v1.z, v1.w);
    *(uint4*)(dst + (size_t)idx * 8) = o;
}

// ======================= fp16 mma GEMM ======================================
#define GO_BIAS  0u
#define GO_STAGE 1024u
#define STAGE_SZ 32768u
#define G_SMEM   (1024 + 2 * 32768)   // 66560

__device__ __forceinline__ void gemm_issue_chunk(
    uint32_t sb, const __half* A, const __half* W,
    int bm, int bn, int K, int c, int s_row, int s_g, uint32_t s_off)
{
    const int kc = c << 6;
    const uint32_t stage = GO_STAGE + (uint32_t)(c & 1) * STAGE_SZ;
#pragma unroll
    for (int it = 0; it < 4; it++) {
        uint32_t off = s_off + (uint32_t)(it * 32 * 128);
        int row = s_row + it * 32;
        cp_async16(sb + stage + off,
                   A + (size_t)(bm + row) * K + kc + s_g * 8);
        cp_async16(sb + stage + 16384 + off,
                   W + (size_t)(bn + row) * K + kc + s_g * 8);
    }
    CP_COMMIT();
}

template<bool GELU, bool RES, bool HASB, bool OUTH>
__global__ __launch_bounds__(256)
void mgemm_kernel(const __half* __restrict__ A, const __half* __restrict__ W,
                  const float* __restrict__ bias, const float* __restrict__ res,
                  float* __restrict__ Cf, __half* __restrict__ Ch,
                  int M, int N, int K)
{
    char* smem = dyn_smem;
    const uint32_t sb = smem_u32(smem);
    const int tid  = threadIdx.x;
    const int lane = tid & 31;
    const int warp = tid >> 5;
    const int bm = blockIdx.y << 7;
    const int bn = blockIdx.x << 7;
    const int wm = (warp >> 2) << 6;
    const int wn = (warp & 3) << 5;

    float* sbias = (float*)(smem + GO_BIAS);
    if (HASB && tid < 128) sbias[tid] = bias[bn + tid];

    float acc[4][4][4];
#pragma unroll
    for (int i = 0; i < 4; i++)
#pragma unroll
        for (int j = 0; j < 4; j++)
#pragma unroll
            for (int k = 0; k < 4; k++) acc[i][j][k] = 0.0f;

    const int a_row = lane & 15;
    const int a_cg  = lane >> 4;
    // paired-B ldsm4 lane mapping: quadrant g = lane>>3
    const int bq_sub = (lane >> 4) & 1;   // 0: nt even, 1: nt odd
    const int bq_cg  = (lane >> 3) & 1;   // k-group within step
    const int bq_row = lane & 7;

    const int s_row = tid >> 3;
    const int s_g   = tid & 7;
    const uint32_t s_off =
        (uint32_t)(s_row * 128 + ((s_g ^ (s_row & 7)) << 4));

    const int nch = K >> 6;

    gemm_issue_chunk(sb, A, W, bm, bn, K, 0, s_row, s_g, s_off);
    for (int c = 0; c < nch; c++) {
        CP_WAIT(0);
        __syncthreads();   // chunk c visible; stage (c+1)&1 free (all done with c-1)
        if (c + 1 < nch)
            gemm_issue_chunk(sb, A, W, bm, bn, K, c + 1, s_row, s_g, s_off);

        const uint32_t sA = sb + GO_STAGE + (uint32_t)(c & 1) * STAGE_SZ;
        const uint32_t sW = sA + 16384;
#pragma unroll
        for (int ks = 0; ks < 4; ks++) {
            uint32_t ah[4][4], wh[2][4];
#pragma unroll
            for (int mt = 0; mt < 4; mt++) {
                int row = wm + mt * 16 + a_row;
                int cg  = ks * 2 + a_cg;
                ldsm4(sA + row * 128 + ((cg ^ (row & 7)) << 4), ah[mt]);
            }
            // paired B: one ldsm4 covers nt pair (2j, 2j+1)
#pragma unroll
            for (int j = 0; j < 2; j++) {
                int row = wn + (2 * j + bq_sub) * 8 + bq_row;
                int cg  = ks * 2 + bq_cg;
                ldsm4(sW + row * 128 + ((cg ^ (row & 7)) << 4), wh[j]);
            }
#pragma unroll
            for (int mt = 0; mt < 4; mt++)
#pragma unroll
                for (int j = 0; j < 2; j++) {
                    mma16816h(acc[mt][2 * j],     ah[mt], &wh[j][0]);
                    mma16816h(acc[mt][2 * j + 1], ah[mt], &wh[j][2]);
                }
        }
    }

    // ---- epilogue ----
#pragma unroll
    for (int mt = 0; mt < 4; mt++) {
        int r = bm + wm + mt * 16 + (lane >> 2);
#pragma unroll
        for (int nt = 0; nt < 4; nt++) {
            int cl = wn + nt * 8 + ((lane & 3) << 1);
            int c  = bn + cl;
            float2 v0 = make_float2(acc[mt][nt][0], acc[mt][nt][1]);
            float2 v1 = make_float2(acc[mt][nt][2], acc[mt][nt][3]);
            if (HASB) {
                float b0 = sbias[cl], b1 = sbias[cl + 1];
                v0.x += b0; v0.y += b1; v1.x += b0; v1.y += b1;
            }
            if (GELU) {
                v0.x = 0.5f * v0.x * (1.0f + erff(v0.x * 0.70710678f));
                v0.y = 0.5f * v0.y * (1.0f + erff(v0.y * 0.70710678f));
                v1.x = 0.5f * v1.x * (1.0f + erff(v1.x * 0.70710678f));
                v1.y = 0.5f * v1.y * (1.0f + erff(v1.y * 0.70710678f));
            }
            size_t i0 = (size_t)r * N + c;
            size_t i1 = (size_t)(r + 8) * N + c;
            if (OUTH) {
                *(uint32_t*)(Ch + i0) = pack2h(v0.x, v0.y);
                *(uint32_t*)(Ch + i1) = pack2h(v1.x, v1.y);
            } else {
                if (RES) {
                    float2 r0 = *(const float2*)(res + i0);
                    float2 r1 = *(const float2*)(res + i1);
                    v0.x += r0.x; v0.y += r0.y; v1.x += r1.x; v1.y += r1.y;
                }
                *(float2*)(Cf + i0) = v0;
                *(float2*)(Cf + i1) = v1;
            }
        }
    }
}

// ---------------- embedding + positional encoding ---------------------------
__global__ __launch_bounds__(256) void embed_kernel(
    const int* __restrict__ x, const float* __restrict__ ew,
    float* __restrict__ h)
{
    int row = blockIdx.x;
    int d   = threadIdx.x;
    int s   = row & (S_ - 1);
    int tok = x[row];
    int p   = d >> 1;
    float dim_t = powf(10000.0f, (float)p * (1.0f / 128.0f));
    float pos   = (float)s / dim_t;
    float pe    = (d & 1) ? cosf(pos) : sinf(pos);
    h[(size_t)row * D_ + d] = ew[(size_t)tok * D_ + d] + pe;
}

// ---------------- LayerNorm + fp32/fp16 emit ---------------------------------
__global__ __launch_bounds__(256) void ln_kernel(
    const float* __restrict__ in, float* __restrict__ out,
    __half* __restrict__ outH,
    const float* __restrict__ w, const float* __restrict__ b)
{
    int warp = threadIdx.x >> 5, lane = threadIdx.x & 31;
    size_t row = (size_t)blockIdx.x * 8 + warp;
    const float* p = in + row * D_;
    float4 a0 = *(const float4*)(p + lane * 4);
    float4 a1 = *(const float4*)(p + 128 + lane * 4);
    float s = a0.x + a0.y + a0.z + a0.w + a1.x + a1.y + a1.z + a1.w;
    float q = a0.x*a0.x + a0.y*a0.y + a0.z*a0.z + a0.w*a0.w
            + a1.x*a1.x + a1.y*a1.y + a1.z*a1.z + a1.w*a1.w;
#pragma unroll
    for (int o = 16; o > 0; o >>= 1) {
        s += __shfl_xor_sync(0xffffffffu, s, o);
        q += __shfl_xor_sync(0xffffffffu, q, o);
    }
    float mean = s * (1.0f / 256.0f);
    float var  = q * (1.0f / 256.0f) - mean * mean;
    float rstd = rsqrtf(var + 1e-5f);
    float4 w0 = *(const float4*)(w + lane * 4);
    float4 w1 = *(const float4*)(w + 128 + lane * 4);
    float4 b0 = *(const float4*)(b + lane * 4);
    float4 b1 = *(const float4*)(b + 128 + lane * 4);
    float4 o0, o1;
    o0.x = (a0.x - mean) * rstd * w0.x + b0.x;
    o0.y = (a0.y - mean) * rstd * w0.y + b0.y;
    o0.z = (a0.z - mean) * rstd * w0.z + b0.z;
    o0.w = (a0.w - mean) * rstd * w0.w + b0.w;
    o1.x = (a1.x - mean) * rstd * w1.x + b1.x;
    o1.y = (a1.y - mean) * rstd * w1.y + b1.y;
    o1.z = (a1.z - mean) * rstd * w1.z + b1.z;
    o1.w = (a1.w - mean) * rstd * w1.w + b1.w;
    float* po = out + row * D_;
    *(float4*)(po + lane * 4)       = o0;
    *(float4*)(po + 128 + lane * 4) = o1;
    *(uint2*)(outH + row * D_ + lane * 4) =
        make_uint2(pack2h(o0.x, o0.y), pack2h(o0.z, o0.w));
    *(uint2*)(outH + row * D_ + 128 + lane * 4) =
        make_uint2(pack2h(o1.x, o1.y), pack2h(o1.z, o1.w));
}

// ---------------- attention: tensor-core FA (mma QK + PV) --------------------
#define ATTN_SMEM (3 * 16384 + 512)   // 49664

__global__ __launch_bounds__(256) void attn_kernel(
    const __half* __restrict__ qkv, const float* __restrict__ ids,
    __half* __restrict__ oh)
{
    char* smem = dyn_smem;
    const uint32_t sb = smem_u32(smem);
    const uint32_t sQ = sb;
    const uint32_t sK = sb + 16384;
    const uint32_t sV = sb + 32768;
    float* msk = (float*)(smem + 49152);
    const int h = blockIdx.x, b = blockIdx.y, t = threadIdx.x;
    const int lane = t & 31, warp = t >> 5;
    const __half* base = qkv + (size_t)b * S_ * 768 + h * DH_;

    for (int idx = t; idx < 1024; idx += 256) {
        int r = idx >> 3, g = idx & 7;
        uint32_t off = (uint32_t)(r * 128 + ((g ^ (r & 7)) << 4));
        const __half* src = base + (size_t)r * 768 + g * 8;
        *(uint4*)(smem + off)         = *(const uint4*)(src);
        *(uint4*)(smem + 16384 + off) = *(const uint4*)(src + 256);
        *(uint4*)(smem + 32768 + off) = *(const uint4*)(src + 512);
    }
    if (t < 128) msk[t] = ids[b * S_ + t] * (-1e9f * SCALE_ * LOG2E_);
    __syncthreads();

    float sacc[16][4];
#pragma unroll
    for (int nt = 0; nt < 16; nt++)
#pragma unroll
        for (int k = 0; k < 4; k++) sacc[nt][k] = 0.0f;

    const int mrow0 = warp * 16;
#pragma unroll
    for (int ks = 0; ks < 4; ks++) {
        uint32_t a[4];
        {
            int row = mrow0 + (lane & 15);
            int cg  = ks * 2 + (lane >> 4);
            ldsm4(sQ + row * 128 + ((cg ^ (row & 7)) << 4), a);
        }
#pragma unroll
        for (int nt = 0; nt < 16; nt++) {
            uint32_t bf[2];
            int row = nt * 8 + (lane & 7);
            int cg  = ks * 2 + ((lane >> 3) & 1);
            ldsm2(sK + row * 128 + ((cg ^ (row & 7)) << 4), bf);
            mma16816h(sacc[nt], a, bf);
        }
    }

    const float kscale = SCALE_ * LOG2E_;
    float m0 = -1e30f, m1 = -1e30f;
    const int cq = (lane & 3) * 2;
#pragma unroll
    for (int nt = 0; nt < 16; nt++) {
        float2 mk = *(float2*)(msk + nt * 8 + cq);
        sacc[nt][0] = fmaf(sacc[nt][0], kscale, mk.x);
        sacc[nt][1] = fmaf(sacc[nt][1], kscale, mk.y);
        sacc[nt][2] = fmaf(sacc[nt][2], kscale, mk.x);
        sacc[nt][3] = fmaf(sacc[nt][3], kscale, mk.y);
        m0 = fmaxf(m0, fmaxf(sacc[nt][0], sacc[nt][1]));
        m1 = fmaxf(m1, fmaxf(sacc[nt][2], sacc[nt][3]));
    }
    m0 = fmaxf(m0, __shfl_xor_sync(0xffffffffu, m0, 1));
    m0 = fmaxf(m0, __shfl_xor_sync(0xffffffffu, m0, 2));
    m1 = fmaxf(m1, __shfl_xor_sync(0xffffffffu, m1, 1));
    m1 = fmaxf(m1, __shfl_xor_sync(0xffffffffu, m1, 2));

    float l0 = 0.0f, l1 = 0.0f;
    uint32_t pa[16], pb[16];
#pragma unroll
    for (int nt = 0; nt < 16; nt++) {
        __half2 d0 = __floats2half2_rn(sacc[nt][0] - m0, sacc[nt][1] - m0);
        __half2 p0 = h2exp2(d0);
        float2 f0 = __half22float2(p0);
        l0 += f0.x + f0.y;
        memcpy(&pa[nt], &p0, 4);
        __half2 d1 = __floats2half2_rn(sacc[nt][2] - m1, sacc[nt][3] - m1);
        __half2 p1 = h2exp2(d1);
        float2 f1 = __half22float2(p1);
        l1 += f1.x + f1.y;
        memcpy(&pb[nt], &p1, 4);
    }
    l0 += __shfl_xor_sync(0xffffffffu, l0, 1);
    l0 += __shfl_xor_sync(0xffffffffu, l0, 2);
    l1 += __shfl_xor_sync(0xffffffffu, l1, 1);
    l1 += __shfl_xor_sync(0xffffffffu, l1, 2);
    float inv0 = 1.0f / l0, inv1 = 1.0f / l1;

    float oacc[8][4];
#pragma unroll
    for (int vt = 0; vt < 8; vt++)
#pragma unroll
        for (int k = 0; k < 4; k++) oacc[vt][k] = 0.0f;

#pragma unroll
    for (int kk = 0; kk < 8; kk++) {
        uint32_t a[4] = {pa[2 * kk], pb[2 * kk], pa[2 * kk + 1], pb[2 * kk + 1]};
        int row = kk * 16 + (lane & 15);
        uint32_t rbase = sV + row * 128;
        uint32_t rsw = (row & 7) << 4;
#pragma unroll
        for (int vt = 0; vt < 8; vt++) {
            uint32_t bf[2];
            ldsm2t(rbase + (((uint32_t)vt << 4) ^ rsw), bf);
            mma16816h(oacc[vt], a, bf);
        }
    }

    size_t rbase = (size_t)(b * S_ + mrow0 + (lane >> 2)) * D_ + h * DH_;
#pragma unroll
    for (int vt = 0; vt < 8; vt++) {
        int col = vt * 8 + cq;
        *(uint32_t*)(oh + rbase + col) =
            pack2h(oacc[vt][0] * inv0, oacc[vt][1] * inv0);
        *(uint32_t*)(oh + rbase + (size_t)8 * D_ + col) =
            pack2h(oacc[vt][2] * inv1, oacc[vt][3] * inv1);
    }
}

// ---------------- final logits ---------------------------------------------
__global__ __launch_bounds__(256) void logits_kernel(
    const float* __restrict__ hflat, const float* __restrict__ W,
    const float* __restrict__ bias, float* __restrict__ out)
{
    int b = blockIdx.x, t = threadIdx.x;
    const float4* h4  = (const float4*)(hflat + (size_t)b * 32768);
    const float4* w04 = (const float4*)(W);
    const float4* w14 = (const float4*)(W + 32768);
    float a0 = 0.0f, a1 = 0.0f;
    for (int i = t; i < 8192; i += 256) {
        float4 x = h4[i], u = w04[i], v = w14[i];
        a0 += x.x*u.x + x.y*u.y + x.z*u.z + x.w*u.w;
        a1 += x.x*v.x + x.y*v.y + x.z*v.z + x.w*v.w;
    }
    __shared__ float r0[256], r1[256];
    r0[t] = a0; r1[t] = a1;
    __syncthreads();
    for (int s = 128; s > 0; s >>= 1) {
        if (t < s) { r0[t] += r0[t + s]; r1[t] += r1[t + s]; }
        __syncthreads();
    }
    if (t == 0) {
        out[b * 2 + 0] = r0[0] + bias[0];
        out[b * 2 + 1] = r1[0] + bias[1];
    }
}

// ---------------- launch ----------------------------------------------------
extern "C" void kernel_launch(void* const* d_in, const int* in_sizes, int n_in,
                              void* d_out, int out_size)
{
    const int*   x    = (const int*)  d_in[0];
    const float* ids  = (const float*)d_in[1];
    const float* ew   = (const float*)d_in[2];
    const float* n1w  = (const float*)d_in[3];
    const float* n1b  = (const float*)d_in[4];
    const float* piw  = (const float*)d_in[5];
    const float* pow_ = (const float*)d_in[6];
    const float* pob  = (const float*)d_in[7];
    const float* n2w  = (const float*)d_in[8];
    const float* n2b  = (const float*)d_in[9];
    const float* l1w  = (const float*)d_in[10];
    const float* l1b  = (const float*)d_in[11];
    const float* l2w  = (const float*)d_in[12];
    const float* l2b  = (const float*)d_in[13];
    const float* lw   = (const float*)d_in[14];
    const float* lb   = (const float*)d_in[15];
    float* out = (float*)d_out;

    float *h, *hn;
    __half *qkvh, *hnH, *tmpH, *wH;
    cudaGetSymbolAddress((void**)&h,    g_h);
    cudaGetSymbolAddress((void**)&hn,   g_hn);
    cudaGetSymbolAddress((void**)&qkvh, g_qkvH);
    cudaGetSymbolAddress((void**)&hnH,  g_hnH);
    cudaGetSymbolAddress((void**)&tmpH, g_tmpH);
    cudaGetSymbolAddress((void**)&wH,   g_wH);

    cudaFuncSetAttribute(attn_kernel,
                         cudaFuncAttributeMaxDynamicSharedMemorySize, ATTN_SMEM);
    cudaFuncSetAttribute(mgemm_kernel<false,false,false,true>,
                         cudaFuncAttributeMaxDynamicSharedMemorySize, G_SMEM);
    cudaFuncSetAttribute(mgemm_kernel<false,true,true,false>,
                         cudaFuncAttributeMaxDynamicSharedMemorySize, G_SMEM);
    cudaFuncSetAttribute(mgemm_kernel<true,false,true,true>,
                         cudaFuncAttributeMaxDynamicSharedMemorySize, G_SMEM);

    // preconvert all weights to fp16 (once per launch)
    wconv_kernel<<<(L_ * D3D_ / 8 + 255) / 256, 256>>>(piw,  wH + OFF_PIW, L_ * D3D_ / 8);
    wconv_kernel<<<(L_ * DD_  / 8 + 255) / 256, 256>>>(pow_, wH + OFF_POW, L_ * DD_ / 8);
    wconv_kernel<<<(L_ * FFD_ / 8 + 255) / 256, 256>>>(l1w,  wH + OFF_L1W, L_ * FFD_ / 8);
    wconv_kernel<<<(L_ * DFF_ / 8 + 255) / 256, 256>>>(l2w,  wH + OFF_L2W, L_ * DFF_ / 8);

    embed_kernel<<<ROWS_, 256>>>(x, ew, h);

    for (int l = 0; l < L_; l++) {
        ln_kernel<<<ROWS_ / 8, 256>>>(h, hn, hnH, n1w + l * D_, n1b + l * D_);
        // qkv (fp16 out)
        mgemm_kernel<false,false,false,true><<<dim3(6, 512), 256, G_SMEM>>>(
            hnH, wH + OFF_PIW + (size_t)l * D3D_,
            nullptr, nullptr, nullptr, qkvh, ROWS_, 3 * D_, D_);
        attn_kernel<<<dim3(H_, B_), 256, ATTN_SMEM>>>(qkvh, ids, tmpH);
        // h = attn_out @ Wo^T + bo + hn (fp32 residual)
        mgemm_kernel<false,true,true,false><<<dim3(2, 512), 256, G_SMEM>>>(
            tmpH, wH + OFF_POW + (size_t)l * DD_,
            pob + l * D_, hn, h, nullptr, ROWS_, D_, D_);
        ln_kernel<<<ROWS_ / 8, 256>>>(h, hn, hnH, n2w + l * D_, n2b + l * D_);
        mgemm_kernel<true,false,true,true><<<dim3(3, 512), 256, G_SMEM>>>(
            hnH, wH + OFF_L1W + (size_t)l * FFD_,
            l1b + l * FF_, nullptr, nullptr, tmpH, ROWS_, FF_, D_);
        mgemm_kernel<false,true,true,false><<<dim3(2, 512), 256, G_SMEM>>>(
            tmpH, wH + OFF_L2W + (size_t)l * DFF_,
            l2b + l * D_, hn, h, nullptr, ROWS_, D_, FF_);
    }

    logits_kernel<<<B_, 256>>>(h, lw, lb, out);
}